// round 12
// baseline (speedup 1.0000x reference)
#include <cuda_runtime.h>
#include <cuda_fp16.h>
#include <math_constants.h>
#include <cstdint>

// Problem constants
#define BB 8
#define SS 1024
#define EE 1024
#define HH 16
#define DD 64
#define MM (BB * SS)   // 8192

// ---------------------------------------------------------------------------
// Scratch (device globals — no allocation allowed)  — fp16 hi/lo splits
// ---------------------------------------------------------------------------
__device__ __half g_Xhi[MM * EE];
__device__ __half g_Xlo[MM * EE];
__device__ __half g_AOhi[MM * EE];
__device__ __half g_AOlo[MM * EE];
// Attention operands, head-major [b][h][s][d]
__device__ __half g_aQh[MM * EE];
__device__ __half g_aQl[MM * EE];
__device__ __half g_aKh[MM * EE];
__device__ __half g_aKl[MM * EE];
__device__ __half g_aVh[MM * EE];
__device__ __half g_aVl[MM * EE];
// Transposed weights: [N][K] fp16 hi/lo. Index: 0=q,1=k,2=v,3=o
__device__ __half g_Whi[4][EE * EE];
__device__ __half g_Wlo[4][EE * EE];
// RoPE tables
__device__ float g_cos[SS * 32];
__device__ float g_sin[SS * 32];

// ---------------------------------------------------------------------------
// Helpers
// ---------------------------------------------------------------------------
__device__ __forceinline__ uint32_t smem_u32(const void* p) {
    uint32_t a;
    asm("{ .reg .u64 t; cvta.to.shared.u64 t, %1; cvt.u32.u64 %0, t; }"
        : "=r"(a) : "l"(p));
    return a;
}

__device__ __forceinline__ void ldsm_x4(uint32_t* r, uint32_t addr) {
    asm volatile("ldmatrix.sync.aligned.m8n8.x4.shared.b16 {%0,%1,%2,%3}, [%4];"
                 : "=r"(r[0]), "=r"(r[1]), "=r"(r[2]), "=r"(r[3]) : "r"(addr));
}

__device__ __forceinline__ void ldsm_x4_t(uint32_t* r, uint32_t addr) {
    asm volatile("ldmatrix.sync.aligned.m8n8.x4.trans.shared.b16 {%0,%1,%2,%3}, [%4];"
                 : "=r"(r[0]), "=r"(r[1]), "=r"(r[2]), "=r"(r[3]) : "r"(addr));
}

// fp16 inputs, fp32 accumulate (half-rate path) — for the hi*hi term
__device__ __forceinline__ void mma_f32acc(float* d, const uint32_t* a,
                                           uint32_t b0, uint32_t b1) {
    asm volatile(
        "mma.sync.aligned.m16n8k16.row.col.f32.f16.f16.f32 "
        "{%0,%1,%2,%3}, {%4,%5,%6,%7}, {%8,%9}, {%0,%1,%2,%3};"
        : "+f"(d[0]), "+f"(d[1]), "+f"(d[2]), "+f"(d[3])
        : "r"(a[0]), "r"(a[1]), "r"(a[2]), "r"(a[3]), "r"(b0), "r"(b1));
}

// fp16 inputs, fp16 accumulate (full-rate path) — for small cross terms
__device__ __forceinline__ void mma_f16acc(uint32_t* d, const uint32_t* a,
                                           uint32_t b0, uint32_t b1) {
    asm volatile(
        "mma.sync.aligned.m16n8k16.row.col.f16.f16.f16.f16 "
        "{%0,%1}, {%2,%3,%4,%5}, {%6,%7}, {%0,%1};"
        : "+r"(d[0]), "+r"(d[1])
        : "r"(a[0]), "r"(a[1]), "r"(a[2]), "r"(a[3]), "r"(b0), "r"(b1));
}

// Split two floats into packed fp16 hi pair + lo pair
__device__ __forceinline__ void pack_hilo(float x, float y,
                                          uint32_t& h, uint32_t& l) {
    __half2 hv = __floats2half2_rn(x, y);
    float2 hf = __half22float2(hv);
    __half2 lv = __floats2half2_rn(x - hf.x, y - hf.y);
    h = *reinterpret_cast<uint32_t*>(&hv);
    l = *reinterpret_cast<uint32_t*>(&lv);
}

__device__ __forceinline__ float2 h2f2(uint32_t v) {
    __half2 h = *reinterpret_cast<__half2*>(&v);
    return __half22float2(h);
}

#define CP_ASYNC16(dst, src) \
    asm volatile("cp.async.cg.shared.global [%0], [%1], 16;\n" \
                 :: "r"(dst), "l"(src) : "memory")
#define CP_COMMIT() asm volatile("cp.async.commit_group;\n" ::: "memory")

// ---------------------------------------------------------------------------
// RoPE cos/sin tables
// ---------------------------------------------------------------------------
__global__ void rope_tab_kernel(const float* __restrict__ freqs,
                                float* __restrict__ ct, float* __restrict__ st)
{
    int i = blockIdx.x * blockDim.x + threadIdx.x;
    if (i >= SS * 32) return;
    float s, c;
    sincosf(freqs[i], &s, &c);
    ct[i] = c;
    st[i] = s;
}

// ---------------------------------------------------------------------------
// fp32 -> fp16 hi/lo split (X only)
// ---------------------------------------------------------------------------
__global__ void split_convert_kernel(const float* __restrict__ X,
                                     __half* __restrict__ hi,
                                     __half* __restrict__ lo, int n4)
{
    int i = blockIdx.x * blockDim.x + threadIdx.x;
    if (i >= n4) return;
    float4 v = *(const float4*)&X[i * 4];
    float vv[4] = {v.x, v.y, v.z, v.w};
    #pragma unroll
    for (int j = 0; j < 4; j++) {
        __half h = __float2half_rn(vv[j]);
        float r = vv[j] - __half2float(h);
        hi[i * 4 + j] = h;
        lo[i * 4 + j] = __float2half_rn(r);
    }
}

// ---------------------------------------------------------------------------
// Weight transpose + split, all 4 weights in one launch (z selects)
// ---------------------------------------------------------------------------
__global__ __launch_bounds__(1024) void transpose_split_kernel(
    const float* __restrict__ w0, const float* __restrict__ w1,
    const float* __restrict__ w2, const float* __restrict__ w3,
    __half* __restrict__ WhiA, __half* __restrict__ WloA)
{
    __shared__ float t[32][33];
    int z = blockIdx.z;
    const float* W = (z == 0) ? w0 : (z == 1) ? w1 : (z == 2) ? w2 : w3;
    __half* Whi = WhiA + (size_t)z * EE * EE;
    __half* Wlo = WloA + (size_t)z * EE * EE;

    int k = blockIdx.y * 32 + threadIdx.y;
    int n = blockIdx.x * 32 + threadIdx.x;
    t[threadIdx.y][threadIdx.x] = W[(size_t)k * EE + n];
    __syncthreads();
    int nn = blockIdx.x * 32 + threadIdx.y;
    int kk = blockIdx.y * 32 + threadIdx.x;
    float v = t[threadIdx.x][threadIdx.y];
    __half h = __float2half_rn(v);
    float r = v - __half2float(h);
    Whi[(size_t)nn * EE + kk] = h;
    Wlo[(size_t)nn * EE + kk] = __float2half_rn(r);
}

// ---------------------------------------------------------------------------
// HMMA fp16-split GEMM, warp tile 32x64.
// hi*hi -> f32 accum (half rate); hi*lo + lo*hi -> f16 accum (full rate),
// merged into fp32 at epilogue.
// ---------------------------------------------------------------------------
#define BKG 32
#define NIT (EE / BKG)          // 32
#define ROWB 80
#define MATB (128 * ROWB)
#define OAH 0
#define OAL (1 * MATB)
#define OBH (2 * MATB)
#define OBL (3 * MATB)
#define STGB (4 * MATB)
#define GSTAGES 3
#define GEMM_SMEM (GSTAGES * STGB)  // 122880 B

template<int EPI>
__global__ __launch_bounds__(256) void gemm_hmma_t(
    const __half* __restrict__ Ahi, const __half* __restrict__ Alo,
    const __half* __restrict__ WhiA, const __half* __restrict__ WloA,
    const float* __restrict__ b0, const float* __restrict__ b1,
    const float* __restrict__ b2,
    float* __restrict__ Cf,
    __half* __restrict__ O0h, __half* __restrict__ O0l,
    __half* __restrict__ O1h, __half* __restrict__ O1l,
    __half* __restrict__ O2h, __half* __restrict__ O2l,
    const float* __restrict__ costab, const float* __restrict__ sintab)
{
    extern __shared__ char smraw[];
    const uint32_t sb = smem_u32(smraw);
    const int tid  = threadIdx.x;
    const int wid  = tid >> 5;
    const int lane = tid & 31;
    const int m0 = blockIdx.y * 128;
    const int n0 = blockIdx.x * 128;
    const int wm = (wid & 3) * 32;
    const int wn = (wid >> 2) * 64;
    const int z  = (EPI == 1) ? blockIdx.z : 0;

    const __half* Bhi = WhiA + (size_t)z * EE * EE;
    const __half* Blo = WloA + (size_t)z * EE * EE;

    const int lr = tid >> 2;
    const int lc = tid & 3;
    const __half* gsrc[4] = {
        Ahi + (size_t)(m0 + lr) * EE + lc * 8,
        Alo + (size_t)(m0 + lr) * EE + lc * 8,
        Bhi + (size_t)(n0 + lr) * EE + lc * 8,
        Blo + (size_t)(n0 + lr) * EE + lc * 8
    };
    const uint32_t dst0 = sb + lr * ROWB + lc * 16;

    const uint32_t a_off = (wm + (lane & 15)) * ROWB + (lane >> 4) * 16;
    const uint32_t b_off = (wn + ((lane >> 4) << 3) + (lane & 7)) * ROWB
                         + ((lane >> 3) & 1) * 16;

    float d[2][8][4];
    uint32_t e[2][8][2];   // f16x2 cross-term accumulators
    #pragma unroll
    for (int mt = 0; mt < 2; mt++)
        #pragma unroll
        for (int nt = 0; nt < 8; nt++) {
            #pragma unroll
            for (int i = 0; i < 4; i++) d[mt][nt][i] = 0.f;
            e[mt][nt][0] = 0u; e[mt][nt][1] = 0u;
        }

    #pragma unroll
    for (int s = 0; s < 2; s++) {
        #pragma unroll
        for (int mat = 0; mat < 4; mat++) {
            #pragma unroll
            for (int p = 0; p < 2; p++) {
                uint32_t dst = dst0 + s * STGB + mat * MATB + p * 64 * ROWB;
                const void* g = gsrc[mat] + (size_t)p * 64 * EE + s * BKG;
                CP_ASYNC16(dst, g);
            }
        }
        CP_COMMIT();
    }

    for (int it = 0; it < NIT; it++) {
        if (it < NIT - 2)
            asm volatile("cp.async.wait_group 1;\n" ::: "memory");
        else
            asm volatile("cp.async.wait_group 0;\n" ::: "memory");
        __syncthreads();

        if (it + 2 < NIT) {
            int s = (it + 2) % GSTAGES;
            int k0 = (it + 2) * BKG;
            #pragma unroll
            for (int mat = 0; mat < 4; mat++) {
                #pragma unroll
                for (int p = 0; p < 2; p++) {
                    uint32_t dst = dst0 + s * STGB + mat * MATB + p * 64 * ROWB;
                    const void* g = gsrc[mat] + (size_t)p * 64 * EE + k0;
                    CP_ASYNC16(dst, g);
                }
            }
            CP_COMMIT();
        }

        const uint32_t st = sb + (it % GSTAGES) * STGB;
        #pragma unroll
        for (int kc = 0; kc < 2; kc++) {
            uint32_t ah[2][4], al[2][4], bh[4][4], bl[4][4];
            #pragma unroll
            for (int mt = 0; mt < 2; mt++) {
                ldsm_x4(ah[mt], st + OAH + a_off + mt * 16 * ROWB + kc * 32);
                ldsm_x4(al[mt], st + OAL + a_off + mt * 16 * ROWB + kc * 32);
            }
            #pragma unroll
            for (int nb = 0; nb < 4; nb++) {
                ldsm_x4(bh[nb], st + OBH + b_off + nb * 16 * ROWB + kc * 32);
                ldsm_x4(bl[nb], st + OBL + b_off + nb * 16 * ROWB + kc * 32);
            }
            // hi*hi -> f32 accum
            #pragma unroll
            for (int mt = 0; mt < 2; mt++)
                #pragma unroll
                for (int nt = 0; nt < 8; nt++) {
                    int nb = nt >> 1, sc = (nt & 1) * 2;
                    mma_f32acc(d[mt][nt], ah[mt], bh[nb][sc], bh[nb][sc + 1]);
                }
            // hi*lo -> f16 accum
            #pragma unroll
            for (int mt = 0; mt < 2; mt++)
                #pragma unroll
                for (int nt = 0; nt < 8; nt++) {
                    int nb = nt >> 1, sc = (nt & 1) * 2;
                    mma_f16acc(e[mt][nt], ah[mt], bl[nb][sc], bl[nb][sc + 1]);
                }
            // lo*hi -> f16 accum
            #pragma unroll
            for (int mt = 0; mt < 2; mt++)
                #pragma unroll
                for (int nt = 0; nt < 8; nt++) {
                    int nb = nt >> 1, sc = (nt & 1) * 2;
                    mma_f16acc(e[mt][nt], al[mt], bh[nb][sc], bh[nb][sc + 1]);
                }
        }
    }

    // merge cross terms into fp32
    #pragma unroll
    for (int mt = 0; mt < 2; mt++)
        #pragma unroll
        for (int nt = 0; nt < 8; nt++) {
            float2 x = h2f2(e[mt][nt][0]);
            float2 y = h2f2(e[mt][nt][1]);
            d[mt][nt][0] += x.x; d[mt][nt][1] += x.y;
            d[mt][nt][2] += y.x; d[mt][nt][3] += y.y;
        }

    if (EPI == 0) {
        #pragma unroll
        for (int mt = 0; mt < 2; mt++) {
            int r = m0 + wm + mt * 16 + (lane >> 2);
            #pragma unroll
            for (int nt = 0; nt < 8; nt++) {
                int c = n0 + wn + nt * 8 + (lane & 3) * 2;
                float2 bb = *(const float2*)&b0[c];
                float2 o0 = {d[mt][nt][0] + bb.x, d[mt][nt][1] + bb.y};
                float2 o1 = {d[mt][nt][2] + bb.x, d[mt][nt][3] + bb.y};
                *(float2*)&Cf[(size_t)r * EE + c] = o0;
                *(float2*)&Cf[(size_t)(r + 8) * EE + c] = o1;
            }
        }
    } else {
        const float* bias = (z == 0) ? b0 : (z == 1) ? b1 : b2;
        #pragma unroll
        for (int mt = 0; mt < 2; mt++)
            #pragma unroll
            for (int nt = 0; nt < 8; nt++) {
                float2 bb = *(const float2*)&bias[n0 + wn + nt * 8 + (lane & 3) * 2];
                d[mt][nt][0] += bb.x; d[mt][nt][1] += bb.y;
                d[mt][nt][2] += bb.x; d[mt][nt][3] += bb.y;
            }

        const int head = (n0 + wn) >> 6;
        __half* Oh = (z == 0) ? O0h : (z == 1) ? O1h : O2h;
        __half* Ol = (z == 0) ? O0l : (z == 1) ? O1l : O2l;

        if (z < 2) {
            #pragma unroll
            for (int mt = 0; mt < 2; mt++) {
                #pragma unroll
                for (int rr = 0; rr < 2; rr++) {
                    int r = m0 + wm + mt * 16 + (lane >> 2) + rr * 8;
                    int b = r >> 10, s = r & (SS - 1);
                    size_t ob = ((size_t)(b * HH + head) * SS + s) * DD;
                    const float* cs = costab + s * 32;
                    const float* sn = sintab + s * 32;
                    #pragma unroll
                    for (int nt = 0; nt < 4; nt++) {
                        int dh = nt * 8 + (lane & 3) * 2;
                        float2 c2 = *(const float2*)&cs[dh];
                        float2 s2 = *(const float2*)&sn[dh];
                        float x1a = d[mt][nt][rr * 2 + 0];
                        float x1b = d[mt][nt][rr * 2 + 1];
                        float x2a = d[mt][nt + 4][rr * 2 + 0];
                        float x2b = d[mt][nt + 4][rr * 2 + 1];
                        float o1a = x1a * c2.x - x2a * s2.x;
                        float o1b = x1b * c2.y - x2b * s2.y;
                        float o2a = x2a * c2.x + x1a * s2.x;
                        float o2b = x2b * c2.y + x1b * s2.y;
                        uint32_t h1, l1, h2, l2;
                        pack_hilo(o1a, o1b, h1, l1);
                        pack_hilo(o2a, o2b, h2, l2);
                        *(uint32_t*)&Oh[ob + dh]      = h1;
                        *(uint32_t*)&Ol[ob + dh]      = l1;
                        *(uint32_t*)&Oh[ob + dh + 32] = h2;
                        *(uint32_t*)&Ol[ob + dh + 32] = l2;
                    }
                }
            }
        } else {
            #pragma unroll
            for (int mt = 0; mt < 2; mt++) {
                #pragma unroll
                for (int rr = 0; rr < 2; rr++) {
                    int r = m0 + wm + mt * 16 + (lane >> 2) + rr * 8;
                    int b = r >> 10, s = r & (SS - 1);
                    size_t ob = ((size_t)(b * HH + head) * SS + s) * DD;
                    #pragma unroll
                    for (int nt = 0; nt < 8; nt++) {
                        int dh = nt * 8 + (lane & 3) * 2;
                        uint32_t h, l;
                        pack_hilo(d[mt][nt][rr * 2 + 0],
                                  d[mt][nt][rr * 2 + 1], h, l);
                        *(uint32_t*)&Oh[ob + dh] = h;
                        *(uint32_t*)&Ol[ob + dh] = l;
                    }
                }
            }
        }
    }
}

// ---------------------------------------------------------------------------
// HMMA FlashAttention-2, fp16 split. hi*hi f32-accum; cross terms f16-accum
// merged per KV-iteration (softmax rescaling stays in fp32 only).
// ---------------------------------------------------------------------------
#define ROWA 144
#define A_QTILE (128 * ROWA)
#define A_KV (64 * ROWA)
#define A_STG (4 * A_KV)
#define ATTN_SMEM (2 * A_QTILE + 2 * A_STG)   // 110592

__global__ __launch_bounds__(256) void attn_hmma_kernel(
    const __half* __restrict__ Qh, const __half* __restrict__ Ql,
    const __half* __restrict__ Kh, const __half* __restrict__ Kl,
    const __half* __restrict__ Vh, const __half* __restrict__ Vl,
    __half* __restrict__ AOh, __half* __restrict__ AOl)
{
    extern __shared__ char smraw[];
    const uint32_t sb = smem_u32(smraw);
    const int tid = threadIdx.x;
    const int wid = tid >> 5;
    const int lane = tid & 31;
    const int bh = blockIdx.y;
    const int b = bh >> 4, h = bh & (HH - 1);
    const int q0 = blockIdx.x * 128;

    const size_t hbase = (size_t)bh * SS * DD;
    const __half* Qhp = Qh + hbase + (size_t)q0 * DD;
    const __half* Qlp = Ql + hbase + (size_t)q0 * DD;
    const __half* kv_src[4] = {Kh + hbase, Kl + hbase,
                               Vh + hbase, Vl + hbase};

    const uint32_t sQh = sb, sQl = sb + A_QTILE;
    const uint32_t sKV = sb + 2 * A_QTILE;

    const int lr = tid >> 2;
    const int lc = tid & 3;

    #pragma unroll
    for (int p = 0; p < 2; p++) {
        int r = lr + p * 64;
        #pragma unroll
        for (int cc = 0; cc < 2; cc++) {
            int ch = lc + cc * 4;
            CP_ASYNC16(sQh + r * ROWA + ch * 16, Qhp + (size_t)r * DD + ch * 8);
            CP_ASYNC16(sQl + r * ROWA + ch * 16, Qlp + (size_t)r * DD + ch * 8);
        }
    }
    #pragma unroll
    for (int mat = 0; mat < 4; mat++) {
        #pragma unroll
        for (int cc = 0; cc < 2; cc++) {
            int ch = lc + cc * 4;
            CP_ASYNC16(sKV + mat * A_KV + lr * ROWA + ch * 16,
                       kv_src[mat] + (size_t)lr * DD + ch * 8);
        }
    }
    CP_COMMIT();
    #pragma unroll
    for (int mat = 0; mat < 4; mat++) {
        #pragma unroll
        for (int cc = 0; cc < 2; cc++) {
            int ch = lc + cc * 4;
            CP_ASYNC16(sKV + A_STG + mat * A_KV + lr * ROWA + ch * 16,
                       kv_src[mat] + (size_t)(64 + lr) * DD + ch * 8);
        }
    }
    CP_COMMIT();

    asm volatile("cp.async.wait_group 1;\n" ::: "memory");
    __syncthreads();

    const uint32_t a_off = (wid * 16 + (lane & 15)) * ROWA + (lane >> 4) * 16;
    uint32_t qh[4][4], ql[4][4];
    #pragma unroll
    for (int kk = 0; kk < 4; kk++) {
        ldsm_x4(qh[kk], sQh + a_off + kk * 32);
        ldsm_x4(ql[kk], sQl + a_off + kk * 32);
    }

    const uint32_t b_off = (((lane >> 4) << 3) + (lane & 7)) * ROWA
                         + ((lane >> 3) & 1) * 16;
    const uint32_t v_off = (lane & 15) * ROWA + (lane >> 4) * 16;

    float m0 = -CUDART_INF_F, m1 = -CUDART_INF_F, l0 = 0.f, l1 = 0.f;
    float o[8][4];
    #pragma unroll
    for (int j = 0; j < 8; j++)
        #pragma unroll
        for (int i = 0; i < 4; i++) o[j][i] = 0.f;

    const float scale = 0.125f;

    for (int it = 0; it < 16; it++) {
        if (it > 0) {
            if (it < 14)
                asm volatile("cp.async.wait_group 1;\n" ::: "memory");
            else
                asm volatile("cp.async.wait_group 0;\n" ::: "memory");
            __syncthreads();
        }
        const uint32_t st = sKV + (it & 1) * A_STG;

        float s[8][4];
        uint32_t s16[8][2];
        #pragma unroll
        for (int j = 0; j < 8; j++) {
            #pragma unroll
            for (int i = 0; i < 4; i++) s[j][i] = 0.f;
            s16[j][0] = 0u; s16[j][1] = 0u;
        }

        // ---- S = Q K^T: hi*hi f32-accum; cross f16-accum
        #pragma unroll
        for (int np = 0; np < 4; np++) {
            #pragma unroll
            for (int kk = 0; kk < 4; kk++) {
                uint32_t kh4[4], kl4[4];
                ldsm_x4(kh4, st + 0 * A_KV + b_off + np * 16 * ROWA + kk * 32);
                ldsm_x4(kl4, st + 1 * A_KV + b_off + np * 16 * ROWA + kk * 32);
                mma_f32acc(s[np * 2 + 0], qh[kk], kh4[0], kh4[1]);
                mma_f32acc(s[np * 2 + 1], qh[kk], kh4[2], kh4[3]);
                mma_f16acc(s16[np * 2 + 0], qh[kk], kl4[0], kl4[1]);
                mma_f16acc(s16[np * 2 + 1], qh[kk], kl4[2], kl4[3]);
                mma_f16acc(s16[np * 2 + 0], ql[kk], kh4[0], kh4[1]);
                mma_f16acc(s16[np * 2 + 1], ql[kk], kh4[2], kh4[3]);
            }
        }
        // merge cross terms
        #pragma unroll
        for (int j = 0; j < 8; j++) {
            float2 x = h2f2(s16[j][0]);
            float2 y = h2f2(s16[j][1]);
            s[j][0] += x.x; s[j][1] += x.y;
            s[j][2] += y.x; s[j][3] += y.y;
        }

        float rmax0 = -CUDART_INF_F, rmax1 = -CUDART_INF_F;
        #pragma unroll
        for (int j = 0; j < 8; j++) {
            #pragma unroll
            for (int i = 0; i < 4; i++) s[j][i] *= scale;
            rmax0 = fmaxf(rmax0, fmaxf(s[j][0], s[j][1]));
            rmax1 = fmaxf(rmax1, fmaxf(s[j][2], s[j][3]));
        }
        rmax0 = fmaxf(rmax0, __shfl_xor_sync(0xffffffffu, rmax0, 1));
        rmax0 = fmaxf(rmax0, __shfl_xor_sync(0xffffffffu, rmax0, 2));
        rmax1 = fmaxf(rmax1, __shfl_xor_sync(0xffffffffu, rmax1, 1));
        rmax1 = fmaxf(rmax1, __shfl_xor_sync(0xffffffffu, rmax1, 2));

        float mn0 = fmaxf(m0, rmax0), mn1 = fmaxf(m1, rmax1);
        float c0 = __expf(m0 - mn0), c1 = __expf(m1 - mn1);
        m0 = mn0; m1 = mn1;

        float rs0 = 0.f, rs1 = 0.f;
        #pragma unroll
        for (int j = 0; j < 8; j++) {
            s[j][0] = __expf(s[j][0] - mn0); rs0 += s[j][0];
            s[j][1] = __expf(s[j][1] - mn0); rs0 += s[j][1];
            s[j][2] = __expf(s[j][2] - mn1); rs1 += s[j][2];
            s[j][3] = __expf(s[j][3] - mn1); rs1 += s[j][3];
        }
        rs0 += __shfl_xor_sync(0xffffffffu, rs0, 1);
        rs0 += __shfl_xor_sync(0xffffffffu, rs0, 2);
        rs1 += __shfl_xor_sync(0xffffffffu, rs1, 1);
        rs1 += __shfl_xor_sync(0xffffffffu, rs1, 2);
        l0 = l0 * c0 + rs0;
        l1 = l1 * c1 + rs1;

        #pragma unroll
        for (int j = 0; j < 8; j++) {
            o[j][0] *= c0; o[j][1] *= c0;
            o[j][2] *= c1; o[j][3] *= c1;
        }

        // ---- O += P V: ph*vh f32-accum; cross f16-accum (fresh per it)
        uint32_t o16[8][2];
        #pragma unroll
        for (int j = 0; j < 8; j++) { o16[j][0] = 0u; o16[j][1] = 0u; }

        #pragma unroll
        for (int kk = 0; kk < 4; kk++) {
            uint32_t ph[4], pl[4];
            pack_hilo(s[2 * kk][0],     s[2 * kk][1],     ph[0], pl[0]);
            pack_hilo(s[2 * kk][2],     s[2 * kk][3],     ph[1], pl[1]);
            pack_hilo(s[2 * kk + 1][0], s[2 * kk + 1][1], ph[2], pl[2]);
            pack_hilo(s[2 * kk + 1][2], s[2 * kk + 1][3], ph[3], pl[3]);
            #pragma unroll
            for (int np = 0; np < 4; np++) {
                uint32_t vh4[4], vl4[4];
                ldsm_x4_t(vh4, st + 2 * A_KV + v_off + kk * 16 * ROWA + np * 32);
                ldsm_x4_t(vl4, st + 3 * A_KV + v_off + kk * 16 * ROWA + np * 32);
                mma_f32acc(o[np * 2 + 0], ph, vh4[0], vh4[1]);
                mma_f32acc(o[np * 2 + 1], ph, vh4[2], vh4[3]);
                mma_f16acc(o16[np * 2 + 0], ph, vl4[0], vl4[1]);
                mma_f16acc(o16[np * 2 + 1], ph, vl4[2], vl4[3]);
                mma_f16acc(o16[np * 2 + 0], pl, vh4[0], vh4[1]);
                mma_f16acc(o16[np * 2 + 1], pl, vh4[2], vh4[3]);
            }
        }
        // merge PV cross terms into fp32 output accumulators
        #pragma unroll
        for (int j = 0; j < 8; j++) {
            float2 x = h2f2(o16[j][0]);
            float2 y = h2f2(o16[j][1]);
            o[j][0] += x.x; o[j][1] += x.y;
            o[j][2] += y.x; o[j][3] += y.y;
        }

        __syncthreads();
        if (it + 2 < 16) {
            uint32_t dstg = sKV + (it & 1) * A_STG;
            #pragma unroll
            for (int mat = 0; mat < 4; mat++) {
                #pragma unroll
                for (int cc = 0; cc < 2; cc++) {
                    int ch = lc + cc * 4;
                    CP_ASYNC16(dstg + mat * A_KV + lr * ROWA + ch * 16,
                               kv_src[mat] + (size_t)((it + 2) * 64 + lr) * DD + ch * 8);
                }
            }
            CP_COMMIT();
        }
    }

    float inv0 = 1.f / l0, inv1 = 1.f / l1;
    int r0 = q0 + wid * 16 + (lane >> 2);
    size_t base0 = (size_t)(b * SS + r0) * EE + h * DD;
    size_t base1 = base0 + (size_t)8 * EE;
    int c0l = (lane & 3) * 2;
    #pragma unroll
    for (int j = 0; j < 8; j++) {
        uint32_t h0, l0b, h1, l1b;
        pack_hilo(o[j][0] * inv0, o[j][1] * inv0, h0, l0b);
        pack_hilo(o[j][2] * inv1, o[j][3] * inv1, h1, l1b);
        *(uint32_t*)&AOh[base0 + j * 8 + c0l] = h0;
        *(uint32_t*)&AOl[base0 + j * 8 + c0l] = l0b;
        *(uint32_t*)&AOh[base1 + j * 8 + c0l] = h1;
        *(uint32_t*)&AOl[base1 + j * 8 + c0l] = l1b;
    }
}

// ---------------------------------------------------------------------------
// Launch
// ---------------------------------------------------------------------------
extern "C" void kernel_launch(void* const* d_in, const int* in_sizes, int n_in,
                              void* d_out, int out_size)
{
    const float* X   = (const float*)d_in[0];
    const float* rot = (const float*)d_in[1];
    const float* W[4]  = {(const float*)d_in[2], (const float*)d_in[4],
                          (const float*)d_in[6], (const float*)d_in[8]};
    const float* Bv[4] = {(const float*)d_in[3], (const float*)d_in[5],
                          (const float*)d_in[7], (const float*)d_in[9]};
    float* out = (float*)d_out;

    __half *Xhi, *Xlo, *AOhi, *AOlo, *Whi, *Wlo;
    __half *aQh, *aQl, *aKh, *aKl, *aVh, *aVl;
    float *ctab, *stab;
    cudaGetSymbolAddress((void**)&Xhi,  g_Xhi);
    cudaGetSymbolAddress((void**)&Xlo,  g_Xlo);
    cudaGetSymbolAddress((void**)&AOhi, g_AOhi);
    cudaGetSymbolAddress((void**)&AOlo, g_AOlo);
    cudaGetSymbolAddress((void**)&Whi,  g_Whi);
    cudaGetSymbolAddress((void**)&Wlo,  g_Wlo);
    cudaGetSymbolAddress((void**)&aQh,  g_aQh);
    cudaGetSymbolAddress((void**)&aQl,  g_aQl);
    cudaGetSymbolAddress((void**)&aKh,  g_aKh);
    cudaGetSymbolAddress((void**)&aKl,  g_aKl);
    cudaGetSymbolAddress((void**)&aVh,  g_aVh);
    cudaGetSymbolAddress((void**)&aVl,  g_aVl);
    cudaGetSymbolAddress((void**)&ctab, g_cos);
    cudaGetSymbolAddress((void**)&stab, g_sin);

    cudaFuncSetAttribute(gemm_hmma_t<0>,
                         cudaFuncAttributeMaxDynamicSharedMemorySize, GEMM_SMEM);
    cudaFuncSetAttribute(gemm_hmma_t<1>,
                         cudaFuncAttributeMaxDynamicSharedMemorySize, GEMM_SMEM);
    cudaFuncSetAttribute(attn_hmma_kernel,
                         cudaFuncAttributeMaxDynamicSharedMemorySize, ATTN_SMEM);

    rope_tab_kernel<<<(SS * 32 + 255) / 256, 256>>>(rot, ctab, stab);
    transpose_split_kernel<<<dim3(32, 32, 4), dim3(32, 32)>>>(
        W[0], W[1], W[2], W[3], Whi, Wlo);
    split_convert_kernel<<<(MM * EE / 4 + 255) / 256, 256>>>(
        X, Xhi, Xlo, MM * EE / 4);

    gemm_hmma_t<1><<<dim3(8, 64, 3), 256, GEMM_SMEM>>>(
        Xhi, Xlo, Whi, Wlo, Bv[0], Bv[1], Bv[2],
        nullptr, aQh, aQl, aKh, aKl, aVh, aVl, ctab, stab);

    attn_hmma_kernel<<<dim3(SS / 128, BB * HH), 256, ATTN_SMEM>>>(
        aQh, aQl, aKh, aKl, aVh, aVl, AOhi, AOlo);

    gemm_hmma_t<0><<<dim3(8, 64, 1), 256, GEMM_SMEM>>>(
        AOhi, AOlo, Whi + 3 * (size_t)EE * EE, Wlo + 3 * (size_t)EE * EE,
        Bv[3], nullptr, nullptr,
        out, nullptr, nullptr, nullptr, nullptr, nullptr, nullptr, ctab, stab);
}

// round 13
// speedup vs baseline: 1.1606x; 1.1606x over previous
#include <cuda_runtime.h>
#include <cuda_fp16.h>
#include <math_constants.h>
#include <cstdint>

// Problem constants
#define BB 8
#define SS 1024
#define EE 1024
#define HH 16
#define DD 64
#define MM (BB * SS)   // 8192

// ---------------------------------------------------------------------------
// Scratch (device globals — no allocation allowed)  — fp16 hi/lo splits
// ---------------------------------------------------------------------------
__device__ __half g_Xhi[MM * EE];
__device__ __half g_Xlo[MM * EE];
__device__ __half g_AOhi[MM * EE];
__device__ __half g_AOlo[MM * EE];
// Attention operands, head-major [b][h][s][d]
__device__ __half g_aQh[MM * EE];
__device__ __half g_aQl[MM * EE];
__device__ __half g_aKh[MM * EE];
__device__ __half g_aKl[MM * EE];
__device__ __half g_aVh[MM * EE];
__device__ __half g_aVl[MM * EE];
// Transposed weights: [N][K] fp16 hi/lo. Index: 0=q,1=k,2=v,3=o
__device__ __half g_Whi[4][EE * EE];
__device__ __half g_Wlo[4][EE * EE];
// RoPE tables
__device__ float g_cos[SS * 32];
__device__ float g_sin[SS * 32];

// ---------------------------------------------------------------------------
// Helpers
// ---------------------------------------------------------------------------
__device__ __forceinline__ uint32_t smem_u32(const void* p) {
    uint32_t a;
    asm("{ .reg .u64 t; cvta.to.shared.u64 t, %1; cvt.u32.u64 %0, t; }"
        : "=r"(a) : "l"(p));
    return a;
}

__device__ __forceinline__ void ldsm_x4(uint32_t* r, uint32_t addr) {
    asm volatile("ldmatrix.sync.aligned.m8n8.x4.shared.b16 {%0,%1,%2,%3}, [%4];"
                 : "=r"(r[0]), "=r"(r[1]), "=r"(r[2]), "=r"(r[3]) : "r"(addr));
}

__device__ __forceinline__ void ldsm_x4_t(uint32_t* r, uint32_t addr) {
    asm volatile("ldmatrix.sync.aligned.m8n8.x4.trans.shared.b16 {%0,%1,%2,%3}, [%4];"
                 : "=r"(r[0]), "=r"(r[1]), "=r"(r[2]), "=r"(r[3]) : "r"(addr));
}

// fp16 inputs, fp32 accumulate
__device__ __forceinline__ void mma_f32acc(float* d, const uint32_t* a,
                                           uint32_t b0, uint32_t b1) {
    asm volatile(
        "mma.sync.aligned.m16n8k16.row.col.f32.f16.f16.f32 "
        "{%0,%1,%2,%3}, {%4,%5,%6,%7}, {%8,%9}, {%0,%1,%2,%3};"
        : "+f"(d[0]), "+f"(d[1]), "+f"(d[2]), "+f"(d[3])
        : "r"(a[0]), "r"(a[1]), "r"(a[2]), "r"(a[3]), "r"(b0), "r"(b1));
}

// Split two floats into packed fp16 hi pair + lo pair
__device__ __forceinline__ void pack_hilo(float x, float y,
                                          uint32_t& h, uint32_t& l) {
    __half2 hv = __floats2half2_rn(x, y);
    float2 hf = __half22float2(hv);
    __half2 lv = __floats2half2_rn(x - hf.x, y - hf.y);
    h = *reinterpret_cast<uint32_t*>(&hv);
    l = *reinterpret_cast<uint32_t*>(&lv);
}

#define CP_ASYNC16(dst, src) \
    asm volatile("cp.async.cg.shared.global [%0], [%1], 16;\n" \
                 :: "r"(dst), "l"(src) : "memory")
#define CP_COMMIT() asm volatile("cp.async.commit_group;\n" ::: "memory")

// ---------------------------------------------------------------------------
// RoPE cos/sin tables
// ---------------------------------------------------------------------------
__global__ void rope_tab_kernel(const float* __restrict__ freqs,
                                float* __restrict__ ct, float* __restrict__ st)
{
    int i = blockIdx.x * blockDim.x + threadIdx.x;
    if (i >= SS * 32) return;
    float s, c;
    sincosf(freqs[i], &s, &c);
    ct[i] = c;
    st[i] = s;
}

// ---------------------------------------------------------------------------
// fp32 -> fp16 hi/lo split (X only)
// ---------------------------------------------------------------------------
__global__ void split_convert_kernel(const float* __restrict__ X,
                                     __half* __restrict__ hi,
                                     __half* __restrict__ lo, int n4)
{
    int i = blockIdx.x * blockDim.x + threadIdx.x;
    if (i >= n4) return;
    float4 v = *(const float4*)&X[i * 4];
    float vv[4] = {v.x, v.y, v.z, v.w};
    #pragma unroll
    for (int j = 0; j < 4; j++) {
        __half h = __float2half_rn(vv[j]);
        float r = vv[j] - __half2float(h);
        hi[i * 4 + j] = h;
        lo[i * 4 + j] = __float2half_rn(r);
    }
}

// ---------------------------------------------------------------------------
// Weight transpose + split, all 4 weights in one launch (z selects)
// ---------------------------------------------------------------------------
__global__ __launch_bounds__(1024) void transpose_split_kernel(
    const float* __restrict__ w0, const float* __restrict__ w1,
    const float* __restrict__ w2, const float* __restrict__ w3,
    __half* __restrict__ WhiA, __half* __restrict__ WloA)
{
    __shared__ float t[32][33];
    int z = blockIdx.z;
    const float* W = (z == 0) ? w0 : (z == 1) ? w1 : (z == 2) ? w2 : w3;
    __half* Whi = WhiA + (size_t)z * EE * EE;
    __half* Wlo = WloA + (size_t)z * EE * EE;

    int k = blockIdx.y * 32 + threadIdx.y;
    int n = blockIdx.x * 32 + threadIdx.x;
    t[threadIdx.y][threadIdx.x] = W[(size_t)k * EE + n];
    __syncthreads();
    int nn = blockIdx.x * 32 + threadIdx.y;
    int kk = blockIdx.y * 32 + threadIdx.x;
    float v = t[threadIdx.x][threadIdx.y];
    __half h = __float2half_rn(v);
    float r = v - __half2float(h);
    Whi[(size_t)nn * EE + kk] = h;
    Wlo[(size_t)nn * EE + kk] = __float2half_rn(r);
}

// ---------------------------------------------------------------------------
// HMMA fp16 3-pass split GEMM, warp tile 32x64.
// 2-stage cp.async double buffer + launch_bounds(256,2) -> 2 CTAs/SM.
// ---------------------------------------------------------------------------
#define BKG 32
#define NIT (EE / BKG)          // 32
#define ROWB 80
#define MATB (128 * ROWB)
#define OAH 0
#define OAL (1 * MATB)
#define OBH (2 * MATB)
#define OBL (3 * MATB)
#define STGB (4 * MATB)
#define GSTAGES 2
#define GEMM_SMEM (GSTAGES * STGB)  // 81920 B

template<int EPI>
__global__ __launch_bounds__(256, 2) void gemm_hmma_t(
    const __half* __restrict__ Ahi, const __half* __restrict__ Alo,
    const __half* __restrict__ WhiA, const __half* __restrict__ WloA,
    const float* __restrict__ b0, const float* __restrict__ b1,
    const float* __restrict__ b2,
    float* __restrict__ Cf,
    __half* __restrict__ O0h, __half* __restrict__ O0l,
    __half* __restrict__ O1h, __half* __restrict__ O1l,
    __half* __restrict__ O2h, __half* __restrict__ O2l,
    const float* __restrict__ costab, const float* __restrict__ sintab)
{
    extern __shared__ char smraw[];
    const uint32_t sb = smem_u32(smraw);
    const int tid  = threadIdx.x;
    const int wid  = tid >> 5;
    const int lane = tid & 31;
    const int m0 = blockIdx.y * 128;
    const int n0 = blockIdx.x * 128;
    const int wm = (wid & 3) * 32;
    const int wn = (wid >> 2) * 64;
    const int z  = (EPI == 1) ? blockIdx.z : 0;

    const __half* Bhi = WhiA + (size_t)z * EE * EE;
    const __half* Blo = WloA + (size_t)z * EE * EE;

    const int lr = tid >> 2;
    const int lc = tid & 3;
    const __half* gsrc[4] = {
        Ahi + (size_t)(m0 + lr) * EE + lc * 8,
        Alo + (size_t)(m0 + lr) * EE + lc * 8,
        Bhi + (size_t)(n0 + lr) * EE + lc * 8,
        Blo + (size_t)(n0 + lr) * EE + lc * 8
    };
    const uint32_t dst0 = sb + lr * ROWB + lc * 16;

    const uint32_t a_off = (wm + (lane & 15)) * ROWB + (lane >> 4) * 16;
    const uint32_t b_off = (wn + ((lane >> 4) << 3) + (lane & 7)) * ROWB
                         + ((lane >> 3) & 1) * 16;

    float d[2][8][4];
    #pragma unroll
    for (int mt = 0; mt < 2; mt++)
        #pragma unroll
        for (int nt = 0; nt < 8; nt++)
            #pragma unroll
            for (int i = 0; i < 4; i++) d[mt][nt][i] = 0.f;

    // Prologue: stages 0 and 1 (two commit groups)
    #pragma unroll
    for (int s = 0; s < 2; s++) {
        #pragma unroll
        for (int mat = 0; mat < 4; mat++) {
            #pragma unroll
            for (int p = 0; p < 2; p++) {
                uint32_t dst = dst0 + s * STGB + mat * MATB + p * 64 * ROWB;
                const void* g = gsrc[mat] + (size_t)p * 64 * EE + s * BKG;
                CP_ASYNC16(dst, g);
            }
        }
        CP_COMMIT();
    }

    for (int it = 0; it < NIT; it++) {
        if (it < NIT - 1)
            asm volatile("cp.async.wait_group 1;\n" ::: "memory");
        else
            asm volatile("cp.async.wait_group 0;\n" ::: "memory");
        __syncthreads();

        const uint32_t st = sb + (it & 1) * STGB;
        #pragma unroll
        for (int kc = 0; kc < 2; kc++) {
            uint32_t ah[2][4], al[2][4], bh[4][4], bl[4][4];
            #pragma unroll
            for (int mt = 0; mt < 2; mt++) {
                ldsm_x4(ah[mt], st + OAH + a_off + mt * 16 * ROWB + kc * 32);
                ldsm_x4(al[mt], st + OAL + a_off + mt * 16 * ROWB + kc * 32);
            }
            #pragma unroll
            for (int nb = 0; nb < 4; nb++) {
                ldsm_x4(bh[nb], st + OBH + b_off + nb * 16 * ROWB + kc * 32);
                ldsm_x4(bl[nb], st + OBL + b_off + nb * 16 * ROWB + kc * 32);
            }
            #pragma unroll
            for (int mt = 0; mt < 2; mt++)
                #pragma unroll
                for (int nt = 0; nt < 8; nt++) {
                    int nb = nt >> 1, sc = (nt & 1) * 2;
                    mma_f32acc(d[mt][nt], ah[mt], bh[nb][sc], bh[nb][sc + 1]);
                }
            #pragma unroll
            for (int mt = 0; mt < 2; mt++)
                #pragma unroll
                for (int nt = 0; nt < 8; nt++) {
                    int nb = nt >> 1, sc = (nt & 1) * 2;
                    mma_f32acc(d[mt][nt], ah[mt], bl[nb][sc], bl[nb][sc + 1]);
                }
            #pragma unroll
            for (int mt = 0; mt < 2; mt++)
                #pragma unroll
                for (int nt = 0; nt < 8; nt++) {
                    int nb = nt >> 1, sc = (nt & 1) * 2;
                    mma_f32acc(d[mt][nt], al[mt], bh[nb][sc], bh[nb][sc + 1]);
                }
        }

        __syncthreads();   // all warps done reading buffer (it&1)

        if (it + 2 < NIT) {
            int k0 = (it + 2) * BKG;
            uint32_t base = sb + (it & 1) * STGB;
            #pragma unroll
            for (int mat = 0; mat < 4; mat++) {
                #pragma unroll
                for (int p = 0; p < 2; p++) {
                    uint32_t dst = dst0 + (base - sb) + mat * MATB + p * 64 * ROWB;
                    const void* g = gsrc[mat] + (size_t)p * 64 * EE + k0;
                    CP_ASYNC16(dst, g);
                }
            }
            CP_COMMIT();
        }
    }

    if (EPI == 0) {
        #pragma unroll
        for (int mt = 0; mt < 2; mt++) {
            int r = m0 + wm + mt * 16 + (lane >> 2);
            #pragma unroll
            for (int nt = 0; nt < 8; nt++) {
                int c = n0 + wn + nt * 8 + (lane & 3) * 2;
                float2 bb = *(const float2*)&b0[c];
                float2 o0 = {d[mt][nt][0] + bb.x, d[mt][nt][1] + bb.y};
                float2 o1 = {d[mt][nt][2] + bb.x, d[mt][nt][3] + bb.y};
                *(float2*)&Cf[(size_t)r * EE + c] = o0;
                *(float2*)&Cf[(size_t)(r + 8) * EE + c] = o1;
            }
        }
    } else {
        const float* bias = (z == 0) ? b0 : (z == 1) ? b1 : b2;
        #pragma unroll
        for (int mt = 0; mt < 2; mt++)
            #pragma unroll
            for (int nt = 0; nt < 8; nt++) {
                float2 bb = *(const float2*)&bias[n0 + wn + nt * 8 + (lane & 3) * 2];
                d[mt][nt][0] += bb.x; d[mt][nt][1] += bb.y;
                d[mt][nt][2] += bb.x; d[mt][nt][3] += bb.y;
            }

        const int head = (n0 + wn) >> 6;
        __half* Oh = (z == 0) ? O0h : (z == 1) ? O1h : O2h;
        __half* Ol = (z == 0) ? O0l : (z == 1) ? O1l : O2l;

        if (z < 2) {
            #pragma unroll
            for (int mt = 0; mt < 2; mt++) {
                #pragma unroll
                for (int rr = 0; rr < 2; rr++) {
                    int r = m0 + wm + mt * 16 + (lane >> 2) + rr * 8;
                    int b = r >> 10, s = r & (SS - 1);
                    size_t ob = ((size_t)(b * HH + head) * SS + s) * DD;
                    const float* cs = costab + s * 32;
                    const float* sn = sintab + s * 32;
                    #pragma unroll
                    for (int nt = 0; nt < 4; nt++) {
                        int dh = nt * 8 + (lane & 3) * 2;
                        float2 c2 = *(const float2*)&cs[dh];
                        float2 s2 = *(const float2*)&sn[dh];
                        float x1a = d[mt][nt][rr * 2 + 0];
                        float x1b = d[mt][nt][rr * 2 + 1];
                        float x2a = d[mt][nt + 4][rr * 2 + 0];
                        float x2b = d[mt][nt + 4][rr * 2 + 1];
                        float o1a = x1a * c2.x - x2a * s2.x;
                        float o1b = x1b * c2.y - x2b * s2.y;
                        float o2a = x2a * c2.x + x1a * s2.x;
                        float o2b = x2b * c2.y + x1b * s2.y;
                        uint32_t h1, l1, h2, l2;
                        pack_hilo(o1a, o1b, h1, l1);
                        pack_hilo(o2a, o2b, h2, l2);
                        *(uint32_t*)&Oh[ob + dh]      = h1;
                        *(uint32_t*)&Ol[ob + dh]      = l1;
                        *(uint32_t*)&Oh[ob + dh + 32] = h2;
                        *(uint32_t*)&Ol[ob + dh + 32] = l2;
                    }
                }
            }
        } else {
            #pragma unroll
            for (int mt = 0; mt < 2; mt++) {
                #pragma unroll
                for (int rr = 0; rr < 2; rr++) {
                    int r = m0 + wm + mt * 16 + (lane >> 2) + rr * 8;
                    int b = r >> 10, s = r & (SS - 1);
                    size_t ob = ((size_t)(b * HH + head) * SS + s) * DD;
                    #pragma unroll
                    for (int nt = 0; nt < 8; nt++) {
                        int dh = nt * 8 + (lane & 3) * 2;
                        uint32_t h, l;
                        pack_hilo(d[mt][nt][rr * 2 + 0],
                                  d[mt][nt][rr * 2 + 1], h, l);
                        *(uint32_t*)&Oh[ob + dh] = h;
                        *(uint32_t*)&Ol[ob + dh] = l;
                    }
                }
            }
        }
    }
}

// ---------------------------------------------------------------------------
// HMMA FlashAttention-2, fp16 hi/lo 3-pass (f32 accum throughout)
// ---------------------------------------------------------------------------
#define ROWA 144
#define A_QTILE (128 * ROWA)
#define A_KV (64 * ROWA)
#define A_STG (4 * A_KV)
#define ATTN_SMEM (2 * A_QTILE + 2 * A_STG)   // 110592

__global__ __launch_bounds__(256) void attn_hmma_kernel(
    const __half* __restrict__ Qh, const __half* __restrict__ Ql,
    const __half* __restrict__ Kh, const __half* __restrict__ Kl,
    const __half* __restrict__ Vh, const __half* __restrict__ Vl,
    __half* __restrict__ AOh, __half* __restrict__ AOl)
{
    extern __shared__ char smraw[];
    const uint32_t sb = smem_u32(smraw);
    const int tid = threadIdx.x;
    const int wid = tid >> 5;
    const int lane = tid & 31;
    const int bh = blockIdx.y;
    const int b = bh >> 4, h = bh & (HH - 1);
    const int q0 = blockIdx.x * 128;

    const size_t hbase = (size_t)bh * SS * DD;
    const __half* Qhp = Qh + hbase + (size_t)q0 * DD;
    const __half* Qlp = Ql + hbase + (size_t)q0 * DD;
    const __half* kv_src[4] = {Kh + hbase, Kl + hbase,
                               Vh + hbase, Vl + hbase};

    const uint32_t sQh = sb, sQl = sb + A_QTILE;
    const uint32_t sKV = sb + 2 * A_QTILE;

    const int lr = tid >> 2;
    const int lc = tid & 3;

    #pragma unroll
    for (int p = 0; p < 2; p++) {
        int r = lr + p * 64;
        #pragma unroll
        for (int cc = 0; cc < 2; cc++) {
            int ch = lc + cc * 4;
            CP_ASYNC16(sQh + r * ROWA + ch * 16, Qhp + (size_t)r * DD + ch * 8);
            CP_ASYNC16(sQl + r * ROWA + ch * 16, Qlp + (size_t)r * DD + ch * 8);
        }
    }
    #pragma unroll
    for (int mat = 0; mat < 4; mat++) {
        #pragma unroll
        for (int cc = 0; cc < 2; cc++) {
            int ch = lc + cc * 4;
            CP_ASYNC16(sKV + mat * A_KV + lr * ROWA + ch * 16,
                       kv_src[mat] + (size_t)lr * DD + ch * 8);
        }
    }
    CP_COMMIT();
    #pragma unroll
    for (int mat = 0; mat < 4; mat++) {
        #pragma unroll
        for (int cc = 0; cc < 2; cc++) {
            int ch = lc + cc * 4;
            CP_ASYNC16(sKV + A_STG + mat * A_KV + lr * ROWA + ch * 16,
                       kv_src[mat] + (size_t)(64 + lr) * DD + ch * 8);
        }
    }
    CP_COMMIT();

    asm volatile("cp.async.wait_group 1;\n" ::: "memory");
    __syncthreads();

    const uint32_t a_off = (wid * 16 + (lane & 15)) * ROWA + (lane >> 4) * 16;
    uint32_t qh[4][4], ql[4][4];
    #pragma unroll
    for (int kk = 0; kk < 4; kk++) {
        ldsm_x4(qh[kk], sQh + a_off + kk * 32);
        ldsm_x4(ql[kk], sQl + a_off + kk * 32);
    }

    const uint32_t b_off = (((lane >> 4) << 3) + (lane & 7)) * ROWA
                         + ((lane >> 3) & 1) * 16;
    const uint32_t v_off = (lane & 15) * ROWA + (lane >> 4) * 16;

    float m0 = -CUDART_INF_F, m1 = -CUDART_INF_F, l0 = 0.f, l1 = 0.f;
    float o[8][4];
    #pragma unroll
    for (int j = 0; j < 8; j++)
        #pragma unroll
        for (int i = 0; i < 4; i++) o[j][i] = 0.f;

    const float scale = 0.125f;

    for (int it = 0; it < 16; it++) {
        if (it > 0) {
            if (it < 14)
                asm volatile("cp.async.wait_group 1;\n" ::: "memory");
            else
                asm volatile("cp.async.wait_group 0;\n" ::: "memory");
            __syncthreads();
        }
        const uint32_t st = sKV + (it & 1) * A_STG;

        float s[8][4];
        #pragma unroll
        for (int j = 0; j < 8; j++)
            #pragma unroll
            for (int i = 0; i < 4; i++) s[j][i] = 0.f;

        #pragma unroll
        for (int np = 0; np < 4; np++) {
            #pragma unroll
            for (int kk = 0; kk < 4; kk++) {
                uint32_t kh4[4], kl4[4];
                ldsm_x4(kh4, st + 0 * A_KV + b_off + np * 16 * ROWA + kk * 32);
                ldsm_x4(kl4, st + 1 * A_KV + b_off + np * 16 * ROWA + kk * 32);
                mma_f32acc(s[np * 2 + 0], qh[kk], kh4[0], kh4[1]);
                mma_f32acc(s[np * 2 + 1], qh[kk], kh4[2], kh4[3]);
                mma_f32acc(s[np * 2 + 0], qh[kk], kl4[0], kl4[1]);
                mma_f32acc(s[np * 2 + 1], qh[kk], kl4[2], kl4[3]);
                mma_f32acc(s[np * 2 + 0], ql[kk], kh4[0], kh4[1]);
                mma_f32acc(s[np * 2 + 1], ql[kk], kh4[2], kh4[3]);
            }
        }

        float rmax0 = -CUDART_INF_F, rmax1 = -CUDART_INF_F;
        #pragma unroll
        for (int j = 0; j < 8; j++) {
            #pragma unroll
            for (int i = 0; i < 4; i++) s[j][i] *= scale;
            rmax0 = fmaxf(rmax0, fmaxf(s[j][0], s[j][1]));
            rmax1 = fmaxf(rmax1, fmaxf(s[j][2], s[j][3]));
        }
        rmax0 = fmaxf(rmax0, __shfl_xor_sync(0xffffffffu, rmax0, 1));
        rmax0 = fmaxf(rmax0, __shfl_xor_sync(0xffffffffu, rmax0, 2));
        rmax1 = fmaxf(rmax1, __shfl_xor_sync(0xffffffffu, rmax1, 1));
        rmax1 = fmaxf(rmax1, __shfl_xor_sync(0xffffffffu, rmax1, 2));

        float mn0 = fmaxf(m0, rmax0), mn1 = fmaxf(m1, rmax1);
        float c0 = __expf(m0 - mn0), c1 = __expf(m1 - mn1);
        m0 = mn0; m1 = mn1;

        float rs0 = 0.f, rs1 = 0.f;
        #pragma unroll
        for (int j = 0; j < 8; j++) {
            s[j][0] = __expf(s[j][0] - mn0); rs0 += s[j][0];
            s[j][1] = __expf(s[j][1] - mn0); rs0 += s[j][1];
            s[j][2] = __expf(s[j][2] - mn1); rs1 += s[j][2];
            s[j][3] = __expf(s[j][3] - mn1); rs1 += s[j][3];
        }
        rs0 += __shfl_xor_sync(0xffffffffu, rs0, 1);
        rs0 += __shfl_xor_sync(0xffffffffu, rs0, 2);
        rs1 += __shfl_xor_sync(0xffffffffu, rs1, 1);
        rs1 += __shfl_xor_sync(0xffffffffu, rs1, 2);
        l0 = l0 * c0 + rs0;
        l1 = l1 * c1 + rs1;

        #pragma unroll
        for (int j = 0; j < 8; j++) {
            o[j][0] *= c0; o[j][1] *= c0;
            o[j][2] *= c1; o[j][3] *= c1;
        }

        #pragma unroll
        for (int kk = 0; kk < 4; kk++) {
            uint32_t ph[4], pl[4];
            pack_hilo(s[2 * kk][0],     s[2 * kk][1],     ph[0], pl[0]);
            pack_hilo(s[2 * kk][2],     s[2 * kk][3],     ph[1], pl[1]);
            pack_hilo(s[2 * kk + 1][0], s[2 * kk + 1][1], ph[2], pl[2]);
            pack_hilo(s[2 * kk + 1][2], s[2 * kk + 1][3], ph[3], pl[3]);
            #pragma unroll
            for (int np = 0; np < 4; np++) {
                uint32_t vh4[4], vl4[4];
                ldsm_x4_t(vh4, st + 2 * A_KV + v_off + kk * 16 * ROWA + np * 32);
                ldsm_x4_t(vl4, st + 3 * A_KV + v_off + kk * 16 * ROWA + np * 32);
                mma_f32acc(o[np * 2 + 0], ph, vh4[0], vh4[1]);
                mma_f32acc(o[np * 2 + 1], ph, vh4[2], vh4[3]);
                mma_f32acc(o[np * 2 + 0], ph, vl4[0], vl4[1]);
                mma_f32acc(o[np * 2 + 1], ph, vl4[2], vl4[3]);
                mma_f32acc(o[np * 2 + 0], pl, vh4[0], vh4[1]);
                mma_f32acc(o[np * 2 + 1], pl, vh4[2], vh4[3]);
            }
        }

        __syncthreads();
        if (it + 2 < 16) {
            uint32_t dstg = sKV + (it & 1) * A_STG;
            #pragma unroll
            for (int mat = 0; mat < 4; mat++) {
                #pragma unroll
                for (int cc = 0; cc < 2; cc++) {
                    int ch = lc + cc * 4;
                    CP_ASYNC16(dstg + mat * A_KV + lr * ROWA + ch * 16,
                               kv_src[mat] + (size_t)((it + 2) * 64 + lr) * DD + ch * 8);
                }
            }
            CP_COMMIT();
        }
    }

    float inv0 = 1.f / l0, inv1 = 1.f / l1;
    int r0 = q0 + wid * 16 + (lane >> 2);
    size_t base0 = (size_t)(b * SS + r0) * EE + h * DD;
    size_t base1 = base0 + (size_t)8 * EE;
    int c0l = (lane & 3) * 2;
    #pragma unroll
    for (int j = 0; j < 8; j++) {
        uint32_t h0, l0b, h1, l1b;
        pack_hilo(o[j][0] * inv0, o[j][1] * inv0, h0, l0b);
        pack_hilo(o[j][2] * inv1, o[j][3] * inv1, h1, l1b);
        *(uint32_t*)&AOh[base0 + j * 8 + c0l] = h0;
        *(uint32_t*)&AOl[base0 + j * 8 + c0l] = l0b;
        *(uint32_t*)&AOh[base1 + j * 8 + c0l] = h1;
        *(uint32_t*)&AOl[base1 + j * 8 + c0l] = l1b;
    }
}

// ---------------------------------------------------------------------------
// Launch
// ---------------------------------------------------------------------------
extern "C" void kernel_launch(void* const* d_in, const int* in_sizes, int n_in,
                              void* d_out, int out_size)
{
    const float* X   = (const float*)d_in[0];
    const float* rot = (const float*)d_in[1];
    const float* W[4]  = {(const float*)d_in[2], (const float*)d_in[4],
                          (const float*)d_in[6], (const float*)d_in[8]};
    const float* Bv[4] = {(const float*)d_in[3], (const float*)d_in[5],
                          (const float*)d_in[7], (const float*)d_in[9]};
    float* out = (float*)d_out;

    __half *Xhi, *Xlo, *AOhi, *AOlo, *Whi, *Wlo;
    __half *aQh, *aQl, *aKh, *aKl, *aVh, *aVl;
    float *ctab, *stab;
    cudaGetSymbolAddress((void**)&Xhi,  g_Xhi);
    cudaGetSymbolAddress((void**)&Xlo,  g_Xlo);
    cudaGetSymbolAddress((void**)&AOhi, g_AOhi);
    cudaGetSymbolAddress((void**)&AOlo, g_AOlo);
    cudaGetSymbolAddress((void**)&Whi,  g_Whi);
    cudaGetSymbolAddress((void**)&Wlo,  g_Wlo);
    cudaGetSymbolAddress((void**)&aQh,  g_aQh);
    cudaGetSymbolAddress((void**)&aQl,  g_aQl);
    cudaGetSymbolAddress((void**)&aKh,  g_aKh);
    cudaGetSymbolAddress((void**)&aKl,  g_aKl);
    cudaGetSymbolAddress((void**)&aVh,  g_aVh);
    cudaGetSymbolAddress((void**)&aVl,  g_aVl);
    cudaGetSymbolAddress((void**)&ctab, g_cos);
    cudaGetSymbolAddress((void**)&stab, g_sin);

    cudaFuncSetAttribute(gemm_hmma_t<0>,
                         cudaFuncAttributeMaxDynamicSharedMemorySize, GEMM_SMEM);
    cudaFuncSetAttribute(gemm_hmma_t<1>,
                         cudaFuncAttributeMaxDynamicSharedMemorySize, GEMM_SMEM);
    cudaFuncSetAttribute(attn_hmma_kernel,
                         cudaFuncAttributeMaxDynamicSharedMemorySize, ATTN_SMEM);

    rope_tab_kernel<<<(SS * 32 + 255) / 256, 256>>>(rot, ctab, stab);
    transpose_split_kernel<<<dim3(32, 32, 4), dim3(32, 32)>>>(
        W[0], W[1], W[2], W[3], Whi, Wlo);
    split_convert_kernel<<<(MM * EE / 4 + 255) / 256, 256>>>(
        X, Xhi, Xlo, MM * EE / 4);

    gemm_hmma_t<1><<<dim3(8, 64, 3), 256, GEMM_SMEM>>>(
        Xhi, Xlo, Whi, Wlo, Bv[0], Bv[1], Bv[2],
        nullptr, aQh, aQl, aKh, aKl, aVh, aVl, ctab, stab);

    attn_hmma_kernel<<<dim3(SS / 128, BB * HH), 256, ATTN_SMEM>>>(
        aQh, aQl, aKh, aKl, aVh, aVl, AOhi, AOlo);

    gemm_hmma_t<0><<<dim3(8, 64, 1), 256, GEMM_SMEM>>>(
        AOhi, AOlo, Whi + 3 * (size_t)EE * EE, Wlo + 3 * (size_t)EE * EE,
        Bv[3], nullptr, nullptr,
        out, nullptr, nullptr, nullptr, nullptr, nullptr, nullptr, ctab, stab);
}

// round 16
// speedup vs baseline: 1.2074x; 1.0403x over previous
#include <cuda_runtime.h>
#include <cuda_fp16.h>
#include <math_constants.h>
#include <cstdint>

// Problem constants
#define BB 8
#define SS 1024
#define EE 1024
#define HH 16
#define DD 64
#define MM (BB * SS)   // 8192

// ---------------------------------------------------------------------------
// Scratch (device globals — no allocation allowed)  — fp16 hi/lo splits
// ---------------------------------------------------------------------------
__device__ __half g_Xhi[MM * EE];
__device__ __half g_Xlo[MM * EE];
__device__ __half g_AOhi[MM * EE];
__device__ __half g_AOlo[MM * EE];
// Attention operands, head-major [b][h][s][d]
__device__ __half g_aQh[MM * EE];
__device__ __half g_aQl[MM * EE];
__device__ __half g_aKh[MM * EE];
__device__ __half g_aKl[MM * EE];
__device__ __half g_aVh[MM * EE];
__device__ __half g_aVl[MM * EE];
// Transposed weights: [N][K] fp16 hi/lo. Index: 0=q,1=k,2=v,3=o
__device__ __half g_Whi[4][EE * EE];
__device__ __half g_Wlo[4][EE * EE];
// RoPE tables
__device__ float g_cos[SS * 32];
__device__ float g_sin[SS * 32];

// ---------------------------------------------------------------------------
// Helpers
// ---------------------------------------------------------------------------
__device__ __forceinline__ uint32_t smem_u32(const void* p) {
    uint32_t a;
    asm("{ .reg .u64 t; cvta.to.shared.u64 t, %1; cvt.u32.u64 %0, t; }"
        : "=r"(a) : "l"(p));
    return a;
}

__device__ __forceinline__ void ldsm_x4(uint32_t* r, uint32_t addr) {
    asm volatile("ldmatrix.sync.aligned.m8n8.x4.shared.b16 {%0,%1,%2,%3}, [%4];"
                 : "=r"(r[0]), "=r"(r[1]), "=r"(r[2]), "=r"(r[3]) : "r"(addr));
}

__device__ __forceinline__ void ldsm_x4_t(uint32_t* r, uint32_t addr) {
    asm volatile("ldmatrix.sync.aligned.m8n8.x4.trans.shared.b16 {%0,%1,%2,%3}, [%4];"
                 : "=r"(r[0]), "=r"(r[1]), "=r"(r[2]), "=r"(r[3]) : "r"(addr));
}

// fp16 inputs, fp32 accumulate
__device__ __forceinline__ void mma_f32acc(float* d, const uint32_t* a,
                                           uint32_t b0, uint32_t b1) {
    asm volatile(
        "mma.sync.aligned.m16n8k16.row.col.f32.f16.f16.f32 "
        "{%0,%1,%2,%3}, {%4,%5,%6,%7}, {%8,%9}, {%0,%1,%2,%3};"
        : "+f"(d[0]), "+f"(d[1]), "+f"(d[2]), "+f"(d[3])
        : "r"(a[0]), "r"(a[1]), "r"(a[2]), "r"(a[3]), "r"(b0), "r"(b1));
}

// Split two floats into packed fp16 hi pair + lo pair
__device__ __forceinline__ void pack_hilo(float x, float y,
                                          uint32_t& h, uint32_t& l) {
    __half2 hv = __floats2half2_rn(x, y);
    float2 hf = __half22float2(hv);
    __half2 lv = __floats2half2_rn(x - hf.x, y - hf.y);
    h = *reinterpret_cast<uint32_t*>(&hv);
    l = *reinterpret_cast<uint32_t*>(&lv);
}

#define CP_ASYNC16(dst, src) \
    asm volatile("cp.async.cg.shared.global [%0], [%1], 16;\n" \
                 :: "r"(dst), "l"(src) : "memory")
#define CP_COMMIT() asm volatile("cp.async.commit_group;\n" ::: "memory")

// ---------------------------------------------------------------------------
// RoPE cos/sin tables
// ---------------------------------------------------------------------------
__global__ void rope_tab_kernel(const float* __restrict__ freqs,
                                float* __restrict__ ct, float* __restrict__ st)
{
    int i = blockIdx.x * blockDim.x + threadIdx.x;
    if (i >= SS * 32) return;
    float s, c;
    sincosf(freqs[i], &s, &c);
    ct[i] = c;
    st[i] = s;
}

// ---------------------------------------------------------------------------
// fp32 -> fp16 hi/lo split (X only)
// ---------------------------------------------------------------------------
__global__ void split_convert_kernel(const float* __restrict__ X,
                                     __half* __restrict__ hi,
                                     __half* __restrict__ lo, int n4)
{
    int i = blockIdx.x * blockDim.x + threadIdx.x;
    if (i >= n4) return;
    float4 v = *(const float4*)&X[i * 4];
    float vv[4] = {v.x, v.y, v.z, v.w};
    #pragma unroll
    for (int j = 0; j < 4; j++) {
        __half h = __float2half_rn(vv[j]);
        float r = vv[j] - __half2float(h);
        hi[i * 4 + j] = h;
        lo[i * 4 + j] = __float2half_rn(r);
    }
}

// ---------------------------------------------------------------------------
// Weight transpose + split, all 4 weights in one launch (z selects)
// ---------------------------------------------------------------------------
__global__ __launch_bounds__(1024) void transpose_split_kernel(
    const float* __restrict__ w0, const float* __restrict__ w1,
    const float* __restrict__ w2, const float* __restrict__ w3,
    __half* __restrict__ WhiA, __half* __restrict__ WloA)
{
    __shared__ float t[32][33];
    int z = blockIdx.z;
    const float* W = (z == 0) ? w0 : (z == 1) ? w1 : (z == 2) ? w2 : w3;
    __half* Whi = WhiA + (size_t)z * EE * EE;
    __half* Wlo = WloA + (size_t)z * EE * EE;

    int k = blockIdx.y * 32 + threadIdx.y;
    int n = blockIdx.x * 32 + threadIdx.x;
    t[threadIdx.y][threadIdx.x] = W[(size_t)k * EE + n];
    __syncthreads();
    int nn = blockIdx.x * 32 + threadIdx.y;
    int kk = blockIdx.y * 32 + threadIdx.x;
    float v = t[threadIdx.x][threadIdx.y];
    __half h = __float2half_rn(v);
    float r = v - __half2float(h);
    Whi[(size_t)nn * EE + kk] = h;
    Wlo[(size_t)nn * EE + kk] = __float2half_rn(r);
}

// ---------------------------------------------------------------------------
// HMMA fp16 3-pass split GEMM, warp tile 32x64.
// 2-stage cp.async double buffer + launch_bounds(256,2) -> 2 CTAs/SM.
// ---------------------------------------------------------------------------
#define BKG 32
#define NIT (EE / BKG)          // 32
#define ROWB 80
#define MATB (128 * ROWB)
#define OAH 0
#define OAL (1 * MATB)
#define OBH (2 * MATB)
#define OBL (3 * MATB)
#define STGB (4 * MATB)
#define GSTAGES 2
#define GEMM_SMEM (GSTAGES * STGB)  // 81920 B

template<int EPI>
__global__ __launch_bounds__(256, 2) void gemm_hmma_t(
    const __half* __restrict__ Ahi, const __half* __restrict__ Alo,
    const __half* __restrict__ WhiA, const __half* __restrict__ WloA,
    const float* __restrict__ b0, const float* __restrict__ b1,
    const float* __restrict__ b2,
    float* __restrict__ Cf,
    __half* __restrict__ O0h, __half* __restrict__ O0l,
    __half* __restrict__ O1h, __half* __restrict__ O1l,
    __half* __restrict__ O2h, __half* __restrict__ O2l,
    const float* __restrict__ costab, const float* __restrict__ sintab)
{
    extern __shared__ char smraw[];
    const uint32_t sb = smem_u32(smraw);
    const int tid  = threadIdx.x;
    const int wid  = tid >> 5;
    const int lane = tid & 31;
    const int m0 = blockIdx.y * 128;
    const int n0 = blockIdx.x * 128;
    const int wm = (wid & 3) * 32;
    const int wn = (wid >> 2) * 64;
    const int z  = (EPI == 1) ? blockIdx.z : 0;

    const __half* Bhi = WhiA + (size_t)z * EE * EE;
    const __half* Blo = WloA + (size_t)z * EE * EE;

    const int lr = tid >> 2;
    const int lc = tid & 3;
    const __half* gsrc[4] = {
        Ahi + (size_t)(m0 + lr) * EE + lc * 8,
        Alo + (size_t)(m0 + lr) * EE + lc * 8,
        Bhi + (size_t)(n0 + lr) * EE + lc * 8,
        Blo + (size_t)(n0 + lr) * EE + lc * 8
    };
    const uint32_t dst0 = sb + lr * ROWB + lc * 16;

    const uint32_t a_off = (wm + (lane & 15)) * ROWB + (lane >> 4) * 16;
    const uint32_t b_off = (wn + ((lane >> 4) << 3) + (lane & 7)) * ROWB
                         + ((lane >> 3) & 1) * 16;

    float d[2][8][4];
    #pragma unroll
    for (int mt = 0; mt < 2; mt++)
        #pragma unroll
        for (int nt = 0; nt < 8; nt++)
            #pragma unroll
            for (int i = 0; i < 4; i++) d[mt][nt][i] = 0.f;

    // Prologue: stages 0 and 1 (two commit groups)
    #pragma unroll
    for (int s = 0; s < 2; s++) {
        #pragma unroll
        for (int mat = 0; mat < 4; mat++) {
            #pragma unroll
            for (int p = 0; p < 2; p++) {
                uint32_t dst = dst0 + s * STGB + mat * MATB + p * 64 * ROWB;
                const void* g = gsrc[mat] + (size_t)p * 64 * EE + s * BKG;
                CP_ASYNC16(dst, g);
            }
        }
        CP_COMMIT();
    }

    for (int it = 0; it < NIT; it++) {
        if (it < NIT - 1)
            asm volatile("cp.async.wait_group 1;\n" ::: "memory");
        else
            asm volatile("cp.async.wait_group 0;\n" ::: "memory");
        __syncthreads();

        const uint32_t st = sb + (it & 1) * STGB;
        #pragma unroll
        for (int kc = 0; kc < 2; kc++) {
            uint32_t ah[2][4], al[2][4], bh[4][4], bl[4][4];
            #pragma unroll
            for (int mt = 0; mt < 2; mt++) {
                ldsm_x4(ah[mt], st + OAH + a_off + mt * 16 * ROWB + kc * 32);
                ldsm_x4(al[mt], st + OAL + a_off + mt * 16 * ROWB + kc * 32);
            }
            #pragma unroll
            for (int nb = 0; nb < 4; nb++) {
                ldsm_x4(bh[nb], st + OBH + b_off + nb * 16 * ROWB + kc * 32);
                ldsm_x4(bl[nb], st + OBL + b_off + nb * 16 * ROWB + kc * 32);
            }
            #pragma unroll
            for (int mt = 0; mt < 2; mt++)
                #pragma unroll
                for (int nt = 0; nt < 8; nt++) {
                    int nb = nt >> 1, sc = (nt & 1) * 2;
                    mma_f32acc(d[mt][nt], ah[mt], bh[nb][sc], bh[nb][sc + 1]);
                }
            #pragma unroll
            for (int mt = 0; mt < 2; mt++)
                #pragma unroll
                for (int nt = 0; nt < 8; nt++) {
                    int nb = nt >> 1, sc = (nt & 1) * 2;
                    mma_f32acc(d[mt][nt], ah[mt], bl[nb][sc], bl[nb][sc + 1]);
                }
            #pragma unroll
            for (int mt = 0; mt < 2; mt++)
                #pragma unroll
                for (int nt = 0; nt < 8; nt++) {
                    int nb = nt >> 1, sc = (nt & 1) * 2;
                    mma_f32acc(d[mt][nt], al[mt], bh[nb][sc], bh[nb][sc + 1]);
                }
        }

        __syncthreads();   // all warps done reading buffer (it&1)

        if (it + 2 < NIT) {
            int k0 = (it + 2) * BKG;
            uint32_t base = sb + (it & 1) * STGB;
            #pragma unroll
            for (int mat = 0; mat < 4; mat++) {
                #pragma unroll
                for (int p = 0; p < 2; p++) {
                    uint32_t dst = dst0 + (base - sb) + mat * MATB + p * 64 * ROWB;
                    const void* g = gsrc[mat] + (size_t)p * 64 * EE + k0;
                    CP_ASYNC16(dst, g);
                }
            }
            CP_COMMIT();
        }
    }

    if (EPI == 0) {
        #pragma unroll
        for (int mt = 0; mt < 2; mt++) {
            int r = m0 + wm + mt * 16 + (lane >> 2);
            #pragma unroll
            for (int nt = 0; nt < 8; nt++) {
                int c = n0 + wn + nt * 8 + (lane & 3) * 2;
                float2 bb = *(const float2*)&b0[c];
                float2 o0 = {d[mt][nt][0] + bb.x, d[mt][nt][1] + bb.y};
                float2 o1 = {d[mt][nt][2] + bb.x, d[mt][nt][3] + bb.y};
                *(float2*)&Cf[(size_t)r * EE + c] = o0;
                *(float2*)&Cf[(size_t)(r + 8) * EE + c] = o1;
            }
        }
    } else {
        const float* bias = (z == 0) ? b0 : (z == 1) ? b1 : b2;
        #pragma unroll
        for (int mt = 0; mt < 2; mt++)
            #pragma unroll
            for (int nt = 0; nt < 8; nt++) {
                float2 bb = *(const float2*)&bias[n0 + wn + nt * 8 + (lane & 3) * 2];
                d[mt][nt][0] += bb.x; d[mt][nt][1] += bb.y;
                d[mt][nt][2] += bb.x; d[mt][nt][3] += bb.y;
            }

        const int head = (n0 + wn) >> 6;
        __half* Oh = (z == 0) ? O0h : (z == 1) ? O1h : O2h;
        __half* Ol = (z == 0) ? O0l : (z == 1) ? O1l : O2l;

        if (z < 2) {
            #pragma unroll
            for (int mt = 0; mt < 2; mt++) {
                #pragma unroll
                for (int rr = 0; rr < 2; rr++) {
                    int r = m0 + wm + mt * 16 + (lane >> 2) + rr * 8;
                    int b = r >> 10, s = r & (SS - 1);
                    size_t ob = ((size_t)(b * HH + head) * SS + s) * DD;
                    const float* cs = costab + s * 32;
                    const float* sn = sintab + s * 32;
                    #pragma unroll
                    for (int nt = 0; nt < 4; nt++) {
                        int dh = nt * 8 + (lane & 3) * 2;
                        float2 c2 = *(const float2*)&cs[dh];
                        float2 s2 = *(const float2*)&sn[dh];
                        float x1a = d[mt][nt][rr * 2 + 0];
                        float x1b = d[mt][nt][rr * 2 + 1];
                        float x2a = d[mt][nt + 4][rr * 2 + 0];
                        float x2b = d[mt][nt + 4][rr * 2 + 1];
                        float o1a = x1a * c2.x - x2a * s2.x;
                        float o1b = x1b * c2.y - x2b * s2.y;
                        float o2a = x2a * c2.x + x1a * s2.x;
                        float o2b = x2b * c2.y + x1b * s2.y;
                        uint32_t h1, l1, h2, l2;
                        pack_hilo(o1a, o1b, h1, l1);
                        pack_hilo(o2a, o2b, h2, l2);
                        *(uint32_t*)&Oh[ob + dh]      = h1;
                        *(uint32_t*)&Ol[ob + dh]      = l1;
                        *(uint32_t*)&Oh[ob + dh + 32] = h2;
                        *(uint32_t*)&Ol[ob + dh + 32] = l2;
                    }
                }
            }
        } else {
            #pragma unroll
            for (int mt = 0; mt < 2; mt++) {
                #pragma unroll
                for (int rr = 0; rr < 2; rr++) {
                    int r = m0 + wm + mt * 16 + (lane >> 2) + rr * 8;
                    int b = r >> 10, s = r & (SS - 1);
                    size_t ob = ((size_t)(b * HH + head) * SS + s) * DD;
                    #pragma unroll
                    for (int nt = 0; nt < 8; nt++) {
                        int dh = nt * 8 + (lane & 3) * 2;
                        uint32_t h, l;
                        pack_hilo(d[mt][nt][rr * 2 + 0],
                                  d[mt][nt][rr * 2 + 1], h, l);
                        *(uint32_t*)&Oh[ob + dh] = h;
                        *(uint32_t*)&Ol[ob + dh] = l;
                    }
                }
            }
        }
    }
}

// ---------------------------------------------------------------------------
// HMMA FlashAttention-2, fp16 hi/lo 3-pass (f32 accum).
// Q fragments NOT preloaded (kk-outer loop) -> fewer live registers;
// launch_bounds(256,2) -> 2 CTAs/SM.
// ---------------------------------------------------------------------------
#define ROWA 144
#define A_QTILE (128 * ROWA)
#define A_KV (64 * ROWA)
#define A_STG (4 * A_KV)
#define ATTN_SMEM (2 * A_QTILE + 2 * A_STG)   // 110592

__global__ __launch_bounds__(256, 2) void attn_hmma_kernel(
    const __half* __restrict__ Qh, const __half* __restrict__ Ql,
    const __half* __restrict__ Kh, const __half* __restrict__ Kl,
    const __half* __restrict__ Vh, const __half* __restrict__ Vl,
    __half* __restrict__ AOh, __half* __restrict__ AOl)
{
    extern __shared__ char smraw[];
    const uint32_t sb = smem_u32(smraw);
    const int tid = threadIdx.x;
    const int wid = tid >> 5;
    const int lane = tid & 31;
    const int bh = blockIdx.y;
    const int b = bh >> 4, h = bh & (HH - 1);
    const int q0 = blockIdx.x * 128;

    const size_t hbase = (size_t)bh * SS * DD;
    const __half* Qhp = Qh + hbase + (size_t)q0 * DD;
    const __half* Qlp = Ql + hbase + (size_t)q0 * DD;
    const __half* kv_src[4] = {Kh + hbase, Kl + hbase,
                               Vh + hbase, Vl + hbase};

    const uint32_t sQh = sb, sQl = sb + A_QTILE;
    const uint32_t sKV = sb + 2 * A_QTILE;

    const int lr = tid >> 2;
    const int lc = tid & 3;

    #pragma unroll
    for (int p = 0; p < 2; p++) {
        int r = lr + p * 64;
        #pragma unroll
        for (int cc = 0; cc < 2; cc++) {
            int ch = lc + cc * 4;
            CP_ASYNC16(sQh + r * ROWA + ch * 16, Qhp + (size_t)r * DD + ch * 8);
            CP_ASYNC16(sQl + r * ROWA + ch * 16, Qlp + (size_t)r * DD + ch * 8);
        }
    }
    #pragma unroll
    for (int mat = 0; mat < 4; mat++) {
        #pragma unroll
        for (int cc = 0; cc < 2; cc++) {
            int ch = lc + cc * 4;
            CP_ASYNC16(sKV + mat * A_KV + lr * ROWA + ch * 16,
                       kv_src[mat] + (size_t)lr * DD + ch * 8);
        }
    }
    CP_COMMIT();
    #pragma unroll
    for (int mat = 0; mat < 4; mat++) {
        #pragma unroll
        for (int cc = 0; cc < 2; cc++) {
            int ch = lc + cc * 4;
            CP_ASYNC16(sKV + A_STG + mat * A_KV + lr * ROWA + ch * 16,
                       kv_src[mat] + (size_t)(64 + lr) * DD + ch * 8);
        }
    }
    CP_COMMIT();

    asm volatile("cp.async.wait_group 1;\n" ::: "memory");
    __syncthreads();

    const uint32_t a_off = (wid * 16 + (lane & 15)) * ROWA + (lane >> 4) * 16;
    const uint32_t b_off = (((lane >> 4) << 3) + (lane & 7)) * ROWA
                         + ((lane >> 3) & 1) * 16;
    const uint32_t v_off = (lane & 15) * ROWA + (lane >> 4) * 16;

    float m0 = -CUDART_INF_F, m1 = -CUDART_INF_F, l0 = 0.f, l1 = 0.f;
    float o[8][4];
    #pragma unroll
    for (int j = 0; j < 8; j++)
        #pragma unroll
        for (int i = 0; i < 4; i++) o[j][i] = 0.f;

    const float scale = 0.125f;

    for (int it = 0; it < 16; it++) {
        if (it > 0) {
            if (it < 14)
                asm volatile("cp.async.wait_group 1;\n" ::: "memory");
            else
                asm volatile("cp.async.wait_group 0;\n" ::: "memory");
            __syncthreads();
        }
        const uint32_t st = sKV + (it & 1) * A_STG;

        float s[8][4];
        #pragma unroll
        for (int j = 0; j < 8; j++)
            #pragma unroll
            for (int i = 0; i < 4; i++) s[j][i] = 0.f;

        // ---- S = Q K^T: kk-outer so Q fragments are transient (8 regs)
        #pragma unroll
        for (int kk = 0; kk < 4; kk++) {
            uint32_t qh4[4], ql4[4];
            ldsm_x4(qh4, sQh + a_off + kk * 32);
            ldsm_x4(ql4, sQl + a_off + kk * 32);
            #pragma unroll
            for (int np = 0; np < 4; np++) {
                uint32_t kh4[4], kl4[4];
                ldsm_x4(kh4, st + 0 * A_KV + b_off + np * 16 * ROWA + kk * 32);
                ldsm_x4(kl4, st + 1 * A_KV + b_off + np * 16 * ROWA + kk * 32);
                mma_f32acc(s[np * 2 + 0], qh4, kh4[0], kh4[1]);
                mma_f32acc(s[np * 2 + 1], qh4, kh4[2], kh4[3]);
                mma_f32acc(s[np * 2 + 0], qh4, kl4[0], kl4[1]);
                mma_f32acc(s[np * 2 + 1], qh4, kl4[2], kl4[3]);
                mma_f32acc(s[np * 2 + 0], ql4, kh4[0], kh4[1]);
                mma_f32acc(s[np * 2 + 1], ql4, kh4[2], kh4[3]);
            }
        }

        float rmax0 = -CUDART_INF_F, rmax1 = -CUDART_INF_F;
        #pragma unroll
        for (int j = 0; j < 8; j++) {
            #pragma unroll
            for (int i = 0; i < 4; i++) s[j][i] *= scale;
            rmax0 = fmaxf(rmax0, fmaxf(s[j][0], s[j][1]));
            rmax1 = fmaxf(rmax1, fmaxf(s[j][2], s[j][3]));
        }
        rmax0 = fmaxf(rmax0, __shfl_xor_sync(0xffffffffu, rmax0, 1));
        rmax0 = fmaxf(rmax0, __shfl_xor_sync(0xffffffffu, rmax0, 2));
        rmax1 = fmaxf(rmax1, __shfl_xor_sync(0xffffffffu, rmax1, 1));
        rmax1 = fmaxf(rmax1, __shfl_xor_sync(0xffffffffu, rmax1, 2));

        float mn0 = fmaxf(m0, rmax0), mn1 = fmaxf(m1, rmax1);
        float c0 = __expf(m0 - mn0), c1 = __expf(m1 - mn1);
        m0 = mn0; m1 = mn1;

        float rs0 = 0.f, rs1 = 0.f;
        #pragma unroll
        for (int j = 0; j < 8; j++) {
            s[j][0] = __expf(s[j][0] - mn0); rs0 += s[j][0];
            s[j][1] = __expf(s[j][1] - mn0); rs0 += s[j][1];
            s[j][2] = __expf(s[j][2] - mn1); rs1 += s[j][2];
            s[j][3] = __expf(s[j][3] - mn1); rs1 += s[j][3];
        }
        rs0 += __shfl_xor_sync(0xffffffffu, rs0, 1);
        rs0 += __shfl_xor_sync(0xffffffffu, rs0, 2);
        rs1 += __shfl_xor_sync(0xffffffffu, rs1, 1);
        rs1 += __shfl_xor_sync(0xffffffffu, rs1, 2);
        l0 = l0 * c0 + rs0;
        l1 = l1 * c1 + rs1;

        #pragma unroll
        for (int j = 0; j < 8; j++) {
            o[j][0] *= c0; o[j][1] *= c0;
            o[j][2] *= c1; o[j][3] *= c1;
        }

        // ---- O += P V (P packed hi/lo per kk, transient)
        #pragma unroll
        for (int kk = 0; kk < 4; kk++) {
            uint32_t ph[4], pl[4];
            pack_hilo(s[2 * kk][0],     s[2 * kk][1],     ph[0], pl[0]);
            pack_hilo(s[2 * kk][2],     s[2 * kk][3],     ph[1], pl[1]);
            pack_hilo(s[2 * kk + 1][0], s[2 * kk + 1][1], ph[2], pl[2]);
            pack_hilo(s[2 * kk + 1][2], s[2 * kk + 1][3], ph[3], pl[3]);
            #pragma unroll
            for (int np = 0; np < 4; np++) {
                uint32_t vh4[4], vl4[4];
                ldsm_x4_t(vh4, st + 2 * A_KV + v_off + kk * 16 * ROWA + np * 32);
                ldsm_x4_t(vl4, st + 3 * A_KV + v_off + kk * 16 * ROWA + np * 32);
                mma_f32acc(o[np * 2 + 0], ph, vh4[0], vh4[1]);
                mma_f32acc(o[np * 2 + 1], ph, vh4[2], vh4[3]);
                mma_f32acc(o[np * 2 + 0], ph, vl4[0], vl4[1]);
                mma_f32acc(o[np * 2 + 1], ph, vl4[2], vl4[3]);
                mma_f32acc(o[np * 2 + 0], pl, vh4[0], vh4[1]);
                mma_f32acc(o[np * 2 + 1], pl, vh4[2], vh4[3]);
            }
        }

        __syncthreads();
        if (it + 2 < 16) {
            uint32_t dstg = sKV + (it & 1) * A_STG;
            #pragma unroll
            for (int mat = 0; mat < 4; mat++) {
                #pragma unroll
                for (int cc = 0; cc < 2; cc++) {
                    int ch = lc + cc * 4;
                    CP_ASYNC16(dstg + mat * A_KV + lr * ROWA + ch * 16,
                               kv_src[mat] + (size_t)((it + 2) * 64 + lr) * DD + ch * 8);
                }
            }
            CP_COMMIT();
        }
    }

    float inv0 = 1.f / l0, inv1 = 1.f / l1;
    int r0 = q0 + wid * 16 + (lane >> 2);
    size_t base0 = (size_t)(b * SS + r0) * EE + h * DD;
    size_t base1 = base0 + (size_t)8 * EE;
    int c0l = (lane & 3) * 2;
    #pragma unroll
    for (int j = 0; j < 8; j++) {
        uint32_t h0, l0b, h1, l1b;
        pack_hilo(o[j][0] * inv0, o[j][1] * inv0, h0, l0b);
        pack_hilo(o[j][2] * inv1, o[j][3] * inv1, h1, l1b);
        *(uint32_t*)&AOh[base0 + j * 8 + c0l] = h0;
        *(uint32_t*)&AOl[base0 + j * 8 + c0l] = l0b;
        *(uint32_t*)&AOh[base1 + j * 8 + c0l] = h1;
        *(uint32_t*)&AOl[base1 + j * 8 + c0l] = l1b;
    }
}

// ---------------------------------------------------------------------------
// Launch
// ---------------------------------------------------------------------------
extern "C" void kernel_launch(void* const* d_in, const int* in_sizes, int n_in,
                              void* d_out, int out_size)
{
    const float* X   = (const float*)d_in[0];
    const float* rot = (const float*)d_in[1];
    const float* W[4]  = {(const float*)d_in[2], (const float*)d_in[4],
                          (const float*)d_in[6], (const float*)d_in[8]};
    const float* Bv[4] = {(const float*)d_in[3], (const float*)d_in[5],
                          (const float*)d_in[7], (const float*)d_in[9]};
    float* out = (float*)d_out;

    __half *Xhi, *Xlo, *AOhi, *AOlo, *Whi, *Wlo;
    __half *aQh, *aQl, *aKh, *aKl, *aVh, *aVl;
    float *ctab, *stab;
    cudaGetSymbolAddress((void**)&Xhi,  g_Xhi);
    cudaGetSymbolAddress((void**)&Xlo,  g_Xlo);
    cudaGetSymbolAddress((void**)&AOhi, g_AOhi);
    cudaGetSymbolAddress((void**)&AOlo, g_AOlo);
    cudaGetSymbolAddress((void**)&Whi,  g_Whi);
    cudaGetSymbolAddress((void**)&Wlo,  g_Wlo);
    cudaGetSymbolAddress((void**)&aQh,  g_aQh);
    cudaGetSymbolAddress((void**)&aQl,  g_aQl);
    cudaGetSymbolAddress((void**)&aKh,  g_aKh);
    cudaGetSymbolAddress((void**)&aKl,  g_aKl);
    cudaGetSymbolAddress((void**)&aVh,  g_aVh);
    cudaGetSymbolAddress((void**)&aVl,  g_aVl);
    cudaGetSymbolAddress((void**)&ctab, g_cos);
    cudaGetSymbolAddress((void**)&stab, g_sin);

    cudaFuncSetAttribute(gemm_hmma_t<0>,
                         cudaFuncAttributeMaxDynamicSharedMemorySize, GEMM_SMEM);
    cudaFuncSetAttribute(gemm_hmma_t<1>,
                         cudaFuncAttributeMaxDynamicSharedMemorySize, GEMM_SMEM);
    cudaFuncSetAttribute(attn_hmma_kernel,
                         cudaFuncAttributeMaxDynamicSharedMemorySize, ATTN_SMEM);

    rope_tab_kernel<<<(SS * 32 + 255) / 256, 256>>>(rot, ctab, stab);
    transpose_split_kernel<<<dim3(32, 32, 4), dim3(32, 32)>>>(
        W[0], W[1], W[2], W[3], Whi, Wlo);
    split_convert_kernel<<<(MM * EE / 4 + 255) / 256, 256>>>(
        X, Xhi, Xlo, MM * EE / 4);

    gemm_hmma_t<1><<<dim3(8, 64, 3), 256, GEMM_SMEM>>>(
        Xhi, Xlo, Whi, Wlo, Bv[0], Bv[1], Bv[2],
        nullptr, aQh, aQl, aKh, aKl, aVh, aVl, ctab, stab);

    attn_hmma_kernel<<<dim3(SS / 128, BB * HH), 256, ATTN_SMEM>>>(
        aQh, aQl, aKh, aKl, aVh, aVl, AOhi, AOlo);

    gemm_hmma_t<0><<<dim3(8, 64, 1), 256, GEMM_SMEM>>>(
        AOhi, AOlo, Whi + 3 * (size_t)EE * EE, Wlo + 3 * (size_t)EE * EE,
        Bv[3], nullptr, nullptr,
        out, nullptr, nullptr, nullptr, nullptr, nullptr, nullptr, ctab, stab);
}

// round 17
// speedup vs baseline: 1.3725x; 1.1368x over previous
#include <cuda_runtime.h>
#include <cuda_fp16.h>
#include <math_constants.h>
#include <cstdint>

// Problem constants
#define BB 8
#define SS 1024
#define EE 1024
#define HH 16
#define DD 64
#define MM (BB * SS)   // 8192

// ---------------------------------------------------------------------------
// Scratch (device globals — no allocation allowed)  — fp16 hi/lo splits
// ---------------------------------------------------------------------------
__device__ __half g_Xhi[MM * EE];
__device__ __half g_Xlo[MM * EE];
__device__ __half g_AOh[MM * EE];          // attention output, plain fp16
// Attention operands, head-major [b][h][s][d]
__device__ __half g_aQh[MM * EE];          // Q plain fp16 (lo dropped)
__device__ __half g_aKh[MM * EE];
__device__ __half g_aKl[MM * EE];
__device__ __half g_aVh[MM * EE];
__device__ __half g_aVl[MM * EE];
// Transposed weights: [N][K] fp16 hi/lo. Index: 0=q,1=k,2=v,3=o
__device__ __half g_Whi[4][EE * EE];
__device__ __half g_Wlo[4][EE * EE];
// RoPE tables
__device__ float g_cos[SS * 32];
__device__ float g_sin[SS * 32];

// ---------------------------------------------------------------------------
// Helpers
// ---------------------------------------------------------------------------
__device__ __forceinline__ uint32_t smem_u32(const void* p) {
    uint32_t a;
    asm("{ .reg .u64 t; cvta.to.shared.u64 t, %1; cvt.u32.u64 %0, t; }"
        : "=r"(a) : "l"(p));
    return a;
}

__device__ __forceinline__ void ldsm_x4(uint32_t* r, uint32_t addr) {
    asm volatile("ldmatrix.sync.aligned.m8n8.x4.shared.b16 {%0,%1,%2,%3}, [%4];"
                 : "=r"(r[0]), "=r"(r[1]), "=r"(r[2]), "=r"(r[3]) : "r"(addr));
}

__device__ __forceinline__ void ldsm_x4_t(uint32_t* r, uint32_t addr) {
    asm volatile("ldmatrix.sync.aligned.m8n8.x4.trans.shared.b16 {%0,%1,%2,%3}, [%4];"
                 : "=r"(r[0]), "=r"(r[1]), "=r"(r[2]), "=r"(r[3]) : "r"(addr));
}

// fp16 inputs, fp32 accumulate
__device__ __forceinline__ void mma_f32acc(float* d, const uint32_t* a,
                                           uint32_t b0, uint32_t b1) {
    asm volatile(
        "mma.sync.aligned.m16n8k16.row.col.f32.f16.f16.f32 "
        "{%0,%1,%2,%3}, {%4,%5,%6,%7}, {%8,%9}, {%0,%1,%2,%3};"
        : "+f"(d[0]), "+f"(d[1]), "+f"(d[2]), "+f"(d[3])
        : "r"(a[0]), "r"(a[1]), "r"(a[2]), "r"(a[3]), "r"(b0), "r"(b1));
}

// Split two floats into packed fp16 hi pair + lo pair
__device__ __forceinline__ void pack_hilo(float x, float y,
                                          uint32_t& h, uint32_t& l) {
    __half2 hv = __floats2half2_rn(x, y);
    float2 hf = __half22float2(hv);
    __half2 lv = __floats2half2_rn(x - hf.x, y - hf.y);
    h = *reinterpret_cast<uint32_t*>(&hv);
    l = *reinterpret_cast<uint32_t*>(&lv);
}

// Pack two floats into fp16x2 (hi only)
__device__ __forceinline__ uint32_t pack_h(float x, float y) {
    __half2 hv = __floats2half2_rn(x, y);
    return *reinterpret_cast<uint32_t*>(&hv);
}

#define CP_ASYNC16(dst, src) \
    asm volatile("cp.async.cg.shared.global [%0], [%1], 16;\n" \
                 :: "r"(dst), "l"(src) : "memory")
#define CP_COMMIT() asm volatile("cp.async.commit_group;\n" ::: "memory")

// ---------------------------------------------------------------------------
// RoPE cos/sin tables
// ---------------------------------------------------------------------------
__global__ void rope_tab_kernel(const float* __restrict__ freqs,
                                float* __restrict__ ct, float* __restrict__ st)
{
    int i = blockIdx.x * blockDim.x + threadIdx.x;
    if (i >= SS * 32) return;
    float s, c;
    sincosf(freqs[i], &s, &c);
    ct[i] = c;
    st[i] = s;
}

// ---------------------------------------------------------------------------
// fp32 -> fp16 hi/lo split (X only)
// ---------------------------------------------------------------------------
__global__ void split_convert_kernel(const float* __restrict__ X,
                                     __half* __restrict__ hi,
                                     __half* __restrict__ lo, int n4)
{
    int i = blockIdx.x * blockDim.x + threadIdx.x;
    if (i >= n4) return;
    float4 v = *(const float4*)&X[i * 4];
    float vv[4] = {v.x, v.y, v.z, v.w};
    #pragma unroll
    for (int j = 0; j < 4; j++) {
        __half h = __float2half_rn(vv[j]);
        float r = vv[j] - __half2float(h);
        hi[i * 4 + j] = h;
        lo[i * 4 + j] = __float2half_rn(r);
    }
}

// ---------------------------------------------------------------------------
// Weight transpose + split, all 4 weights in one launch (z selects)
// ---------------------------------------------------------------------------
__global__ __launch_bounds__(1024) void transpose_split_kernel(
    const float* __restrict__ w0, const float* __restrict__ w1,
    const float* __restrict__ w2, const float* __restrict__ w3,
    __half* __restrict__ WhiA, __half* __restrict__ WloA)
{
    __shared__ float t[32][33];
    int z = blockIdx.z;
    const float* W = (z == 0) ? w0 : (z == 1) ? w1 : (z == 2) ? w2 : w3;
    __half* Whi = WhiA + (size_t)z * EE * EE;
    __half* Wlo = WloA + (size_t)z * EE * EE;

    int k = blockIdx.y * 32 + threadIdx.y;
    int n = blockIdx.x * 32 + threadIdx.x;
    t[threadIdx.y][threadIdx.x] = W[(size_t)k * EE + n];
    __syncthreads();
    int nn = blockIdx.x * 32 + threadIdx.y;
    int kk = blockIdx.y * 32 + threadIdx.x;
    float v = t[threadIdx.x][threadIdx.y];
    __half h = __float2half_rn(v);
    float r = v - __half2float(h);
    Whi[(size_t)nn * EE + kk] = h;
    Wlo[(size_t)nn * EE + kk] = __float2half_rn(r);
}

// ---------------------------------------------------------------------------
// HMMA fp16 split GEMM, warp tile 32x64, 2-stage double buffer, 2 CTAs/SM.
// EPI=1 (QKV): 3-pass (hh, hl, lh). Epilogues: z=0 Q->RoPE,fp16; z=1 K->RoPE,
//   hi/lo; z=2 V->hi/lo.
// EPI=0 (O-proj): 2-pass (hh, hl) — A is plain fp16 (AOl dropped); fp32 out.
// ---------------------------------------------------------------------------
#define BKG 32
#define NIT (EE / BKG)          // 32
#define ROWB 80
#define MATB (128 * ROWB)
#define OAH 0
#define OAL (1 * MATB)
#define OBH (2 * MATB)
#define OBL (3 * MATB)
#define STGB (4 * MATB)
#define GSTAGES 2
#define GEMM_SMEM (GSTAGES * STGB)  // 81920 B

template<int EPI>
__global__ __launch_bounds__(256, 2) void gemm_hmma_t(
    const __half* __restrict__ Ahi, const __half* __restrict__ Alo,
    const __half* __restrict__ WhiA, const __half* __restrict__ WloA,
    const float* __restrict__ b0, const float* __restrict__ b1,
    const float* __restrict__ b2,
    float* __restrict__ Cf,
    __half* __restrict__ O0h,
    __half* __restrict__ O1h, __half* __restrict__ O1l,
    __half* __restrict__ O2h, __half* __restrict__ O2l,
    const float* __restrict__ costab, const float* __restrict__ sintab)
{
    extern __shared__ char smraw[];
    const uint32_t sb = smem_u32(smraw);
    const int tid  = threadIdx.x;
    const int wid  = tid >> 5;
    const int lane = tid & 31;
    const int m0 = blockIdx.y * 128;
    const int n0 = blockIdx.x * 128;
    const int wm = (wid & 3) * 32;
    const int wn = (wid >> 2) * 64;
    const int z  = (EPI == 1) ? blockIdx.z : 0;

    const __half* Bhi = WhiA + (size_t)z * EE * EE;
    const __half* Blo = WloA + (size_t)z * EE * EE;

    const int lr = tid >> 2;
    const int lc = tid & 3;
    const __half* gsrc[4] = {
        Ahi + (size_t)(m0 + lr) * EE + lc * 8,
        (EPI == 1) ? Alo + (size_t)(m0 + lr) * EE + lc * 8 : (const __half*)0,
        Bhi + (size_t)(n0 + lr) * EE + lc * 8,
        Blo + (size_t)(n0 + lr) * EE + lc * 8
    };
    const uint32_t dst0 = sb + lr * ROWB + lc * 16;

    const uint32_t a_off = (wm + (lane & 15)) * ROWB + (lane >> 4) * 16;
    const uint32_t b_off = (wn + ((lane >> 4) << 3) + (lane & 7)) * ROWB
                         + ((lane >> 3) & 1) * 16;

    float d[2][8][4];
    #pragma unroll
    for (int mt = 0; mt < 2; mt++)
        #pragma unroll
        for (int nt = 0; nt < 8; nt++)
            #pragma unroll
            for (int i = 0; i < 4; i++) d[mt][nt][i] = 0.f;

    // Prologue: stages 0 and 1 (two commit groups)
    #pragma unroll
    for (int s = 0; s < 2; s++) {
        #pragma unroll
        for (int mat = 0; mat < 4; mat++) {
            if (EPI == 0 && mat == 1) continue;   // no Alo in 2-pass
            #pragma unroll
            for (int p = 0; p < 2; p++) {
                uint32_t dst = dst0 + s * STGB + mat * MATB + p * 64 * ROWB;
                const void* g = gsrc[mat] + (size_t)p * 64 * EE + s * BKG;
                CP_ASYNC16(dst, g);
            }
        }
        CP_COMMIT();
    }

    for (int it = 0; it < NIT; it++) {
        if (it < NIT - 1)
            asm volatile("cp.async.wait_group 1;\n" ::: "memory");
        else
            asm volatile("cp.async.wait_group 0;\n" ::: "memory");
        __syncthreads();

        const uint32_t st = sb + (it & 1) * STGB;
        #pragma unroll
        for (int kc = 0; kc < 2; kc++) {
            uint32_t ah[2][4], al[2][4], bh[4][4], bl[4][4];
            #pragma unroll
            for (int mt = 0; mt < 2; mt++) {
                ldsm_x4(ah[mt], st + OAH + a_off + mt * 16 * ROWB + kc * 32);
                if (EPI == 1)
                    ldsm_x4(al[mt], st + OAL + a_off + mt * 16 * ROWB + kc * 32);
            }
            #pragma unroll
            for (int nb = 0; nb < 4; nb++) {
                ldsm_x4(bh[nb], st + OBH + b_off + nb * 16 * ROWB + kc * 32);
                ldsm_x4(bl[nb], st + OBL + b_off + nb * 16 * ROWB + kc * 32);
            }
            #pragma unroll
            for (int mt = 0; mt < 2; mt++)
                #pragma unroll
                for (int nt = 0; nt < 8; nt++) {
                    int nb = nt >> 1, sc = (nt & 1) * 2;
                    mma_f32acc(d[mt][nt], ah[mt], bh[nb][sc], bh[nb][sc + 1]);
                }
            #pragma unroll
            for (int mt = 0; mt < 2; mt++)
                #pragma unroll
                for (int nt = 0; nt < 8; nt++) {
                    int nb = nt >> 1, sc = (nt & 1) * 2;
                    mma_f32acc(d[mt][nt], ah[mt], bl[nb][sc], bl[nb][sc + 1]);
                }
            if (EPI == 1) {
                #pragma unroll
                for (int mt = 0; mt < 2; mt++)
                    #pragma unroll
                    for (int nt = 0; nt < 8; nt++) {
                        int nb = nt >> 1, sc = (nt & 1) * 2;
                        mma_f32acc(d[mt][nt], al[mt], bh[nb][sc], bh[nb][sc + 1]);
                    }
            }
        }

        __syncthreads();   // all warps done reading buffer (it&1)

        if (it + 2 < NIT) {
            int k0 = (it + 2) * BKG;
            #pragma unroll
            for (int mat = 0; mat < 4; mat++) {
                if (EPI == 0 && mat == 1) continue;
                #pragma unroll
                for (int p = 0; p < 2; p++) {
                    uint32_t dst = dst0 + (it & 1) * STGB + mat * MATB + p * 64 * ROWB;
                    const void* g = gsrc[mat] + (size_t)p * 64 * EE + k0;
                    CP_ASYNC16(dst, g);
                }
            }
            CP_COMMIT();
        }
    }

    if (EPI == 0) {
        #pragma unroll
        for (int mt = 0; mt < 2; mt++) {
            int r = m0 + wm + mt * 16 + (lane >> 2);
            #pragma unroll
            for (int nt = 0; nt < 8; nt++) {
                int c = n0 + wn + nt * 8 + (lane & 3) * 2;
                float2 bb = *(const float2*)&b0[c];
                float2 o0 = {d[mt][nt][0] + bb.x, d[mt][nt][1] + bb.y};
                float2 o1 = {d[mt][nt][2] + bb.x, d[mt][nt][3] + bb.y};
                *(float2*)&Cf[(size_t)r * EE + c] = o0;
                *(float2*)&Cf[(size_t)(r + 8) * EE + c] = o1;
            }
        }
    } else {
        const float* bias = (z == 0) ? b0 : (z == 1) ? b1 : b2;
        #pragma unroll
        for (int mt = 0; mt < 2; mt++)
            #pragma unroll
            for (int nt = 0; nt < 8; nt++) {
                float2 bb = *(const float2*)&bias[n0 + wn + nt * 8 + (lane & 3) * 2];
                d[mt][nt][0] += bb.x; d[mt][nt][1] += bb.y;
                d[mt][nt][2] += bb.x; d[mt][nt][3] += bb.y;
            }

        const int head = (n0 + wn) >> 6;

        if (z < 2) {
            // RoPE; z=0 (Q): store fp16 hi only; z=1 (K): store hi+lo
            #pragma unroll
            for (int mt = 0; mt < 2; mt++) {
                #pragma unroll
                for (int rr = 0; rr < 2; rr++) {
                    int r = m0 + wm + mt * 16 + (lane >> 2) + rr * 8;
                    int b = r >> 10, s = r & (SS - 1);
                    size_t ob = ((size_t)(b * HH + head) * SS + s) * DD;
                    const float* cs = costab + s * 32;
                    const float* sn = sintab + s * 32;
                    #pragma unroll
                    for (int nt = 0; nt < 4; nt++) {
                        int dh = nt * 8 + (lane & 3) * 2;
                        float2 c2 = *(const float2*)&cs[dh];
                        float2 s2 = *(const float2*)&sn[dh];
                        float x1a = d[mt][nt][rr * 2 + 0];
                        float x1b = d[mt][nt][rr * 2 + 1];
                        float x2a = d[mt][nt + 4][rr * 2 + 0];
                        float x2b = d[mt][nt + 4][rr * 2 + 1];
                        float o1a = x1a * c2.x - x2a * s2.x;
                        float o1b = x1b * c2.y - x2b * s2.y;
                        float o2a = x2a * c2.x + x1a * s2.x;
                        float o2b = x2b * c2.y + x1b * s2.y;
                        if (z == 0) {
                            *(uint32_t*)&O0h[ob + dh]      = pack_h(o1a, o1b);
                            *(uint32_t*)&O0h[ob + dh + 32] = pack_h(o2a, o2b);
                        } else {
                            uint32_t h1, l1, h2, l2;
                            pack_hilo(o1a, o1b, h1, l1);
                            pack_hilo(o2a, o2b, h2, l2);
                            *(uint32_t*)&O1h[ob + dh]      = h1;
                            *(uint32_t*)&O1l[ob + dh]      = l1;
                            *(uint32_t*)&O1h[ob + dh + 32] = h2;
                            *(uint32_t*)&O1l[ob + dh + 32] = l2;
                        }
                    }
                }
            }
        } else {
            // V: hi/lo split, head-major store
            #pragma unroll
            for (int mt = 0; mt < 2; mt++) {
                #pragma unroll
                for (int rr = 0; rr < 2; rr++) {
                    int r = m0 + wm + mt * 16 + (lane >> 2) + rr * 8;
                    int b = r >> 10, s = r & (SS - 1);
                    size_t ob = ((size_t)(b * HH + head) * SS + s) * DD;
                    #pragma unroll
                    for (int nt = 0; nt < 8; nt++) {
                        int dh = nt * 8 + (lane & 3) * 2;
                        uint32_t h, l;
                        pack_hilo(d[mt][nt][rr * 2 + 0],
                                  d[mt][nt][rr * 2 + 1], h, l);
                        *(uint32_t*)&O2h[ob + dh] = h;
                        *(uint32_t*)&O2l[ob + dh] = l;
                    }
                }
            }
        }
    }
}

// ---------------------------------------------------------------------------
// HMMA FlashAttention-2.
// Q plain fp16 (2-pass QK^T: qh*kh + qh*kl); P plain fp16 (2-pass PV:
// ph*vh + ph*vl). fp32 softmax/accum. Output AO plain fp16. 2 CTAs/SM.
// ---------------------------------------------------------------------------
#define ROWA 144
#define A_QTILE (128 * ROWA)
#define A_KV (64 * ROWA)
#define A_STG (4 * A_KV)
#define ATTN_SMEM (A_QTILE + 2 * A_STG)   // 92160

__global__ __launch_bounds__(256, 2) void attn_hmma_kernel(
    const __half* __restrict__ Qh,
    const __half* __restrict__ Kh, const __half* __restrict__ Kl,
    const __half* __restrict__ Vh, const __half* __restrict__ Vl,
    __half* __restrict__ AOh)
{
    extern __shared__ char smraw[];
    const uint32_t sb = smem_u32(smraw);
    const int tid = threadIdx.x;
    const int wid = tid >> 5;
    const int lane = tid & 31;
    const int bh = blockIdx.y;
    const int b = bh >> 4, h = bh & (HH - 1);
    const int q0 = blockIdx.x * 128;

    const size_t hbase = (size_t)bh * SS * DD;
    const __half* Qhp = Qh + hbase + (size_t)q0 * DD;
    const __half* kv_src[4] = {Kh + hbase, Kl + hbase,
                               Vh + hbase, Vl + hbase};

    const uint32_t sQh = sb;
    const uint32_t sKV = sb + A_QTILE;

    const int lr = tid >> 2;
    const int lc = tid & 3;

    #pragma unroll
    for (int p = 0; p < 2; p++) {
        int r = lr + p * 64;
        #pragma unroll
        for (int cc = 0; cc < 2; cc++) {
            int ch = lc + cc * 4;
            CP_ASYNC16(sQh + r * ROWA + ch * 16, Qhp + (size_t)r * DD + ch * 8);
        }
    }
    #pragma unroll
    for (int mat = 0; mat < 4; mat++) {
        #pragma unroll
        for (int cc = 0; cc < 2; cc++) {
            int ch = lc + cc * 4;
            CP_ASYNC16(sKV + mat * A_KV + lr * ROWA + ch * 16,
                       kv_src[mat] + (size_t)lr * DD + ch * 8);
        }
    }
    CP_COMMIT();
    #pragma unroll
    for (int mat = 0; mat < 4; mat++) {
        #pragma unroll
        for (int cc = 0; cc < 2; cc++) {
            int ch = lc + cc * 4;
            CP_ASYNC16(sKV + A_STG + mat * A_KV + lr * ROWA + ch * 16,
                       kv_src[mat] + (size_t)(64 + lr) * DD + ch * 8);
        }
    }
    CP_COMMIT();

    asm volatile("cp.async.wait_group 1;\n" ::: "memory");
    __syncthreads();

    const uint32_t a_off = (wid * 16 + (lane & 15)) * ROWA + (lane >> 4) * 16;
    const uint32_t b_off = (((lane >> 4) << 3) + (lane & 7)) * ROWA
                         + ((lane >> 3) & 1) * 16;
    const uint32_t v_off = (lane & 15) * ROWA + (lane >> 4) * 16;

    float m0 = -CUDART_INF_F, m1 = -CUDART_INF_F, l0 = 0.f, l1 = 0.f;
    float o[8][4];
    #pragma unroll
    for (int j = 0; j < 8; j++)
        #pragma unroll
        for (int i = 0; i < 4; i++) o[j][i] = 0.f;

    const float scale = 0.125f;

    for (int it = 0; it < 16; it++) {
        if (it > 0) {
            if (it < 14)
                asm volatile("cp.async.wait_group 1;\n" ::: "memory");
            else
                asm volatile("cp.async.wait_group 0;\n" ::: "memory");
            __syncthreads();
        }
        const uint32_t st = sKV + (it & 1) * A_STG;

        float s[8][4];
        #pragma unroll
        for (int j = 0; j < 8; j++)
            #pragma unroll
            for (int i = 0; i < 4; i++) s[j][i] = 0.f;

        // ---- S = Q K^T (2-pass: qh*kh + qh*kl)
        #pragma unroll
        for (int kk = 0; kk < 4; kk++) {
            uint32_t qh4[4];
            ldsm_x4(qh4, sQh + a_off + kk * 32);
            #pragma unroll
            for (int np = 0; np < 4; np++) {
                uint32_t kh4[4], kl4[4];
                ldsm_x4(kh4, st + 0 * A_KV + b_off + np * 16 * ROWA + kk * 32);
                ldsm_x4(kl4, st + 1 * A_KV + b_off + np * 16 * ROWA + kk * 32);
                mma_f32acc(s[np * 2 + 0], qh4, kh4[0], kh4[1]);
                mma_f32acc(s[np * 2 + 1], qh4, kh4[2], kh4[3]);
                mma_f32acc(s[np * 2 + 0], qh4, kl4[0], kl4[1]);
                mma_f32acc(s[np * 2 + 1], qh4, kl4[2], kl4[3]);
            }
        }

        float rmax0 = -CUDART_INF_F, rmax1 = -CUDART_INF_F;
        #pragma unroll
        for (int j = 0; j < 8; j++) {
            #pragma unroll
            for (int i = 0; i < 4; i++) s[j][i] *= scale;
            rmax0 = fmaxf(rmax0, fmaxf(s[j][0], s[j][1]));
            rmax1 = fmaxf(rmax1, fmaxf(s[j][2], s[j][3]));
        }
        rmax0 = fmaxf(rmax0, __shfl_xor_sync(0xffffffffu, rmax0, 1));
        rmax0 = fmaxf(rmax0, __shfl_xor_sync(0xffffffffu, rmax0, 2));
        rmax1 = fmaxf(rmax1, __shfl_xor_sync(0xffffffffu, rmax1, 1));
        rmax1 = fmaxf(rmax1, __shfl_xor_sync(0xffffffffu, rmax1, 2));

        float mn0 = fmaxf(m0, rmax0), mn1 = fmaxf(m1, rmax1);
        float c0 = __expf(m0 - mn0), c1 = __expf(m1 - mn1);
        m0 = mn0; m1 = mn1;

        float rs0 = 0.f, rs1 = 0.f;
        #pragma unroll
        for (int j = 0; j < 8; j++) {
            s[j][0] = __expf(s[j][0] - mn0); rs0 += s[j][0];
            s[j][1] = __expf(s[j][1] - mn0); rs0 += s[j][1];
            s[j][2] = __expf(s[j][2] - mn1); rs1 += s[j][2];
            s[j][3] = __expf(s[j][3] - mn1); rs1 += s[j][3];
        }
        rs0 += __shfl_xor_sync(0xffffffffu, rs0, 1);
        rs0 += __shfl_xor_sync(0xffffffffu, rs0, 2);
        rs1 += __shfl_xor_sync(0xffffffffu, rs1, 1);
        rs1 += __shfl_xor_sync(0xffffffffu, rs1, 2);
        l0 = l0 * c0 + rs0;
        l1 = l1 * c1 + rs1;

        #pragma unroll
        for (int j = 0; j < 8; j++) {
            o[j][0] *= c0; o[j][1] *= c0;
            o[j][2] *= c1; o[j][3] *= c1;
        }

        // ---- O += P V (2-pass: ph*vh + ph*vl; P plain fp16)
        #pragma unroll
        for (int kk = 0; kk < 4; kk++) {
            uint32_t ph[4];
            ph[0] = pack_h(s[2 * kk][0],     s[2 * kk][1]);
            ph[1] = pack_h(s[2 * kk][2],     s[2 * kk][3]);
            ph[2] = pack_h(s[2 * kk + 1][0], s[2 * kk + 1][1]);
            ph[3] = pack_h(s[2 * kk + 1][2], s[2 * kk + 1][3]);
            #pragma unroll
            for (int np = 0; np < 4; np++) {
                uint32_t vh4[4], vl4[4];
                ldsm_x4_t(vh4, st + 2 * A_KV + v_off + kk * 16 * ROWA + np * 32);
                ldsm_x4_t(vl4, st + 3 * A_KV + v_off + kk * 16 * ROWA + np * 32);
                mma_f32acc(o[np * 2 + 0], ph, vh4[0], vh4[1]);
                mma_f32acc(o[np * 2 + 1], ph, vh4[2], vh4[3]);
                mma_f32acc(o[np * 2 + 0], ph, vl4[0], vl4[1]);
                mma_f32acc(o[np * 2 + 1], ph, vl4[2], vl4[3]);
            }
        }

        __syncthreads();
        if (it + 2 < 16) {
            uint32_t dstg = sKV + (it & 1) * A_STG;
            #pragma unroll
            for (int mat = 0; mat < 4; mat++) {
                #pragma unroll
                for (int cc = 0; cc < 2; cc++) {
                    int ch = lc + cc * 4;
                    CP_ASYNC16(dstg + mat * A_KV + lr * ROWA + ch * 16,
                               kv_src[mat] + (size_t)((it + 2) * 64 + lr) * DD + ch * 8);
                }
            }
            CP_COMMIT();
        }
    }

    // epilogue: normalize, plain fp16 store
    float inv0 = 1.f / l0, inv1 = 1.f / l1;
    int r0 = q0 + wid * 16 + (lane >> 2);
    size_t base0 = (size_t)(b * SS + r0) * EE + h * DD;
    size_t base1 = base0 + (size_t)8 * EE;
    int c0l = (lane & 3) * 2;
    #pragma unroll
    for (int j = 0; j < 8; j++) {
        *(uint32_t*)&AOh[base0 + j * 8 + c0l] =
            pack_h(o[j][0] * inv0, o[j][1] * inv0);
        *(uint32_t*)&AOh[base1 + j * 8 + c0l] =
            pack_h(o[j][2] * inv1, o[j][3] * inv1);
    }
}

// ---------------------------------------------------------------------------
// Launch
// ---------------------------------------------------------------------------
extern "C" void kernel_launch(void* const* d_in, const int* in_sizes, int n_in,
                              void* d_out, int out_size)
{
    const float* X   = (const float*)d_in[0];
    const float* rot = (const float*)d_in[1];
    const float* W[4]  = {(const float*)d_in[2], (const float*)d_in[4],
                          (const float*)d_in[6], (const float*)d_in[8]};
    const float* Bv[4] = {(const float*)d_in[3], (const float*)d_in[5],
                          (const float*)d_in[7], (const float*)d_in[9]};
    float* out = (float*)d_out;

    __half *Xhi, *Xlo, *AOh, *Whi, *Wlo;
    __half *aQh, *aKh, *aKl, *aVh, *aVl;
    float *ctab, *stab;
    cudaGetSymbolAddress((void**)&Xhi,  g_Xhi);
    cudaGetSymbolAddress((void**)&Xlo,  g_Xlo);
    cudaGetSymbolAddress((void**)&AOh,  g_AOh);
    cudaGetSymbolAddress((void**)&Whi,  g_Whi);
    cudaGetSymbolAddress((void**)&Wlo,  g_Wlo);
    cudaGetSymbolAddress((void**)&aQh,  g_aQh);
    cudaGetSymbolAddress((void**)&aKh,  g_aKh);
    cudaGetSymbolAddress((void**)&aKl,  g_aKl);
    cudaGetSymbolAddress((void**)&aVh,  g_aVh);
    cudaGetSymbolAddress((void**)&aVl,  g_aVl);
    cudaGetSymbolAddress((void**)&ctab, g_cos);
    cudaGetSymbolAddress((void**)&stab, g_sin);

    cudaFuncSetAttribute(gemm_hmma_t<0>,
                         cudaFuncAttributeMaxDynamicSharedMemorySize, GEMM_SMEM);
    cudaFuncSetAttribute(gemm_hmma_t<1>,
                         cudaFuncAttributeMaxDynamicSharedMemorySize, GEMM_SMEM);
    cudaFuncSetAttribute(attn_hmma_kernel,
                         cudaFuncAttributeMaxDynamicSharedMemorySize, ATTN_SMEM);

    rope_tab_kernel<<<(SS * 32 + 255) / 256, 256>>>(rot, ctab, stab);
    transpose_split_kernel<<<dim3(32, 32, 4), dim3(32, 32)>>>(
        W[0], W[1], W[2], W[3], Whi, Wlo);
    split_convert_kernel<<<(MM * EE / 4 + 255) / 256, 256>>>(
        X, Xhi, Xlo, MM * EE / 4);

    gemm_hmma_t<1><<<dim3(8, 64, 3), 256, GEMM_SMEM>>>(
        Xhi, Xlo, Whi, Wlo, Bv[0], Bv[1], Bv[2],
        nullptr, aQh, aKh, aKl, aVh, aVl, ctab, stab);

    attn_hmma_kernel<<<dim3(SS / 128, BB * HH), 256, ATTN_SMEM>>>(
        aQh, aKh, aKl, aVh, aVl, AOh);

    gemm_hmma_t<0><<<dim3(8, 64, 1), 256, GEMM_SMEM>>>(
        AOh, nullptr, Whi + 3 * (size_t)EE * EE, Wlo + 3 * (size_t)EE * EE,
        Bv[3], nullptr, nullptr,
        out, nullptr, nullptr, nullptr, nullptr, nullptr, ctab, stab);
}